// round 1
// baseline (speedup 1.0000x reference)
#include <cuda_runtime.h>
#include <cuda_bf16.h>
#include <math.h>

// ---------------------------------------------------------------------------
// Problem constants
// ---------------------------------------------------------------------------
#define NB      2            // batch
#define CDIM    768
#define DD      16
#define HH      14
#define WW      14
#define SPAT    (DD*HH*WW)        // 3136
#define NTOKTOT (NB*SPAT)         // 6272
#define NWIN    16                // total windows (2 batches * 8)
#define NWINB   8                 // windows per batch
#define NTOK    392               // tokens per window (8*7*7)
#define NHEADS  24
#define HDIM    32
#define QKVC    (3*CDIM)          // 2304
#define MLPC    (4*CDIM)          // 3072
#define RPBN    2535
#define BIAS_HN (NTOK*NTOK)       // 153664

// ---------------------------------------------------------------------------
// Static device scratch (no runtime allocation allowed)
// ---------------------------------------------------------------------------
__device__ __align__(128) float g_xcur[NTOKTOT*CDIM];
__device__ __align__(128) float g_bufA[NTOKTOT*CDIM];
__device__ __align__(128) float g_bufB[NTOKTOT*CDIM];
__device__ __align__(128) float g_big [NTOKTOT*MLPC];
__device__ __align__(128) float g_bias[NHEADS*BIAS_HN];
__device__ __align__(128) float g_c1  [NTOKTOT*64];
__device__ __align__(128) float g_out2[2*NTOKTOT*2];
__device__ __align__(128) int   g_map0[NTOKTOT];
__device__ __align__(128) int   g_map1[NTOKTOT];
__device__ __align__(128) int   g_lab [NWINB*NTOK];

__device__ __forceinline__ float gelu_f(float x) {
    return 0.5f * x * (1.0f + erff(x * 0.70710678118654752440f));
}

// ---------------------------------------------------------------------------
// Init: window gather/scatter maps + shift-mask region labels
// ---------------------------------------------------------------------------
__global__ void build_maps_kernel(int* map0, int* map1, int* lab) {
    int r = blockIdx.x * blockDim.x + threadIdx.x;
    if (r < NTOKTOT) {
        int b = r / SPAT, rem = r % SPAT;
        int wi = rem / NTOK, n = rem % NTOK;
        int bd = wi >> 2, bh = (wi >> 1) & 1, bw = wi & 1;
        int wd = n / 49, wh = (n / 7) % 7, ww = n % 7;
        int d = bd * 8 + wd, h = bh * 7 + wh, w = bw * 7 + ww;
        map0[r] = b * SPAT + d * (HH*WW) + h * WW + w;
        int ds = (d + 4) & 15, hs = (h + 3) % 14, ws = (w + 3) % 14;
        map1[r] = b * SPAT + ds * (HH*WW) + hs * WW + ws;
    }
    if (r < NWINB * NTOK) {
        int wi = r / NTOK, n = r % NTOK;
        int bd = wi >> 2, bh = (wi >> 1) & 1, bw = wi & 1;
        int wd = n / 49, wh = (n / 7) % 7, ww = n % 7;
        int d = bd * 8 + wd, h = bh * 7 + wh, w = bw * 7 + ww;
        int cd = d < 8 ? 0 : (d < 12 ? 1 : 2);
        int ch = h < 7 ? 0 : (h < 11 ? 1 : 2);
        int cw = w < 7 ? 0 : (w < 11 ? 1 : 2);
        lab[r] = cd * 9 + ch * 3 + cw;
    }
}

// (B, C, S) -> (B, S, C) tiled transpose
__global__ void transpose_in_kernel(const float* __restrict__ x, float* __restrict__ out) {
    __shared__ float tile[32][33];
    int b  = blockIdx.z;
    int s0 = blockIdx.x * 32, c0 = blockIdx.y * 32;
    int tx = threadIdx.x, ty = threadIdx.y;
    #pragma unroll
    for (int i = 0; i < 32; i += 8) {
        int c = c0 + ty + i, s = s0 + tx;
        if (c < CDIM && s < SPAT)
            tile[ty + i][tx] = x[((size_t)b * CDIM + c) * SPAT + s];
    }
    __syncthreads();
    #pragma unroll
    for (int i = 0; i < 32; i += 8) {
        int s = s0 + ty + i, c = c0 + tx;
        if (s < SPAT && c < CDIM)
            out[((size_t)b * SPAT + s) * CDIM + c] = tile[tx][ty + i];
    }
}

// biasT[h][n][m] = rpb[rpi[n][m]][h]
__global__ void bias_gather_kernel(const float* __restrict__ rpb,
                                   const int* __restrict__ rpi,
                                   float* __restrict__ biasT) {
    int idx = blockIdx.x * blockDim.x + threadIdx.x;
    if (idx >= NHEADS * BIAS_HN) return;
    int h  = idx / BIAS_HN;
    int nm = idx % BIAS_HN;
    biasT[idx] = rpb[rpi[nm] * NHEADS + h];
}

// ---------------------------------------------------------------------------
// LayerNorm (row = one token, 768 channels), optional gather map
// ---------------------------------------------------------------------------
__global__ void __launch_bounds__(256) ln_kernel(const float* __restrict__ in,
                                                 const float* __restrict__ gw,
                                                 const float* __restrict__ gb,
                                                 float* __restrict__ out,
                                                 const int* __restrict__ map) {
    int r = blockIdx.x;
    int src = map ? map[r] : r;
    const float* x = in + (size_t)src * CDIM;
    int t = threadIdx.x;
    float v0 = x[t], v1 = x[t + 256], v2 = x[t + 512];
    __shared__ float red[8];
    __shared__ float stat[2];
    float s = v0 + v1 + v2;
    #pragma unroll
    for (int o = 16; o; o >>= 1) s += __shfl_xor_sync(0xffffffffu, s, o);
    if ((t & 31) == 0) red[t >> 5] = s;
    __syncthreads();
    if (t < 8) {
        float z = red[t];
        z += __shfl_xor_sync(0xffu, z, 4);
        z += __shfl_xor_sync(0xffu, z, 2);
        z += __shfl_xor_sync(0xffu, z, 1);
        if (t == 0) stat[0] = z * (1.0f / CDIM);
    }
    __syncthreads();
    float mu = stat[0];
    float d0 = v0 - mu, d1 = v1 - mu, d2 = v2 - mu;
    s = d0 * d0 + d1 * d1 + d2 * d2;
    #pragma unroll
    for (int o = 16; o; o >>= 1) s += __shfl_xor_sync(0xffffffffu, s, o);
    if ((t & 31) == 0) red[t >> 5] = s;
    __syncthreads();
    if (t < 8) {
        float z = red[t];
        z += __shfl_xor_sync(0xffu, z, 4);
        z += __shfl_xor_sync(0xffu, z, 2);
        z += __shfl_xor_sync(0xffu, z, 1);
        if (t == 0) stat[1] = rsqrtf(z * (1.0f / CDIM) + 1e-5f);
    }
    __syncthreads();
    float inv = stat[1];
    float* o = out + (size_t)r * CDIM;
    o[t]       = d0 * inv * gw[t]       + gb[t];
    o[t + 256] = d1 * inv * gw[t + 256] + gb[t + 256];
    o[t + 512] = d2 * inv * gw[t + 512] + gb[t + 512];
}

// ---------------------------------------------------------------------------
// GEMM: C[m][n] = sum_k A[m][k] * W[n][k] (+bias) (opt gelu) (opt residual/scatter)
// BM=128 BN=64 BK=16, 256 threads, 8x4 per thread
// ---------------------------------------------------------------------------
#define GBM 128
#define GBN 64
#define GBK 16
#define A_STRIDE 132
#define B_STRIDE 68

__global__ void __launch_bounds__(256) gemm_kernel(
    const float* __restrict__ A, const float* __restrict__ W,
    const float* __restrict__ bias, float* __restrict__ C,
    int M, int N, int K, int ldC,
    int act_gelu, const int* __restrict__ scatter, int add_resid)
{
    __shared__ float As[GBK * A_STRIDE];
    __shared__ float Bs[GBK * B_STRIDE];
    int tid = threadIdx.x;
    int tx = tid & 15, ty = tid >> 4;
    int m0 = blockIdx.y * GBM, n0 = blockIdx.x * GBN;
    const float* Aptr = A + (size_t)m0 * K;
    const float* Wptr = W + (size_t)n0 * K;
    float acc[8][4];
    #pragma unroll
    for (int i = 0; i < 8; i++)
        #pragma unroll
        for (int j = 0; j < 4; j++) acc[i][j] = 0.0f;

    for (int k0 = 0; k0 < K; k0 += GBK) {
        #pragma unroll
        for (int l = 0; l < 2; l++) {
            int f = tid + l * 256;
            int row = f >> 2, kc = (f & 3) * 4;
            float4 v = *(const float4*)(Aptr + (size_t)row * K + k0 + kc);
            As[(kc + 0) * A_STRIDE + row] = v.x;
            As[(kc + 1) * A_STRIDE + row] = v.y;
            As[(kc + 2) * A_STRIDE + row] = v.z;
            As[(kc + 3) * A_STRIDE + row] = v.w;
        }
        {
            int row = tid >> 2, kc = (tid & 3) * 4;
            float4 v = *(const float4*)(Wptr + (size_t)row * K + k0 + kc);
            Bs[(kc + 0) * B_STRIDE + row] = v.x;
            Bs[(kc + 1) * B_STRIDE + row] = v.y;
            Bs[(kc + 2) * B_STRIDE + row] = v.z;
            Bs[(kc + 3) * B_STRIDE + row] = v.w;
        }
        __syncthreads();
        #pragma unroll
        for (int kk = 0; kk < GBK; kk++) {
            float4 a0 = *(const float4*)&As[kk * A_STRIDE + ty * 8];
            float4 a1 = *(const float4*)&As[kk * A_STRIDE + ty * 8 + 4];
            float4 bb = *(const float4*)&Bs[kk * B_STRIDE + tx * 4];
            float a[8] = {a0.x, a0.y, a0.z, a0.w, a1.x, a1.y, a1.z, a1.w};
            float b[4] = {bb.x, bb.y, bb.z, bb.w};
            #pragma unroll
            for (int i = 0; i < 8; i++)
                #pragma unroll
                for (int j = 0; j < 4; j++)
                    acc[i][j] += a[i] * b[j];
        }
        __syncthreads();
    }
    // epilogue
    #pragma unroll
    for (int i = 0; i < 8; i++) {
        int gr = m0 + ty * 8 + i;
        int tr = scatter ? scatter[gr] : gr;
        float* cp = C + (size_t)tr * ldC + n0 + tx * 4;
        #pragma unroll
        for (int j = 0; j < 4; j++) {
            float v = acc[i][j] + bias[n0 + tx * 4 + j];
            if (act_gelu) v = gelu_f(v);
            if (add_resid) v += cp[j];
            cp[j] = v;
        }
    }
}

// ---------------------------------------------------------------------------
// Window attention: one block per (head, window). 256 threads (8 warps).
// Warp handles queries n = warp, warp+8, ...; lanes cover keys in chunks of 4.
// ---------------------------------------------------------------------------
#define KT_STRIDE 396

__global__ void __launch_bounds__(256, 1) attn_kernel(
    const float* __restrict__ qkv, int ldq,
    const float* __restrict__ biasT,
    const int* __restrict__ labels,
    float* __restrict__ out, int shifted)
{
    extern __shared__ float sm[];
    float* Kt = sm;
    float* Vt = sm + 32 * KT_STRIDE;
    int*   lab = (int*)(sm + 64 * KT_STRIDE);
    int h = blockIdx.x, w = blockIdx.y;
    int tid = threadIdx.x;
    int rbase = w * NTOK;

    for (int i = tid; i < NTOK * 32; i += 256) {
        int m = i >> 5, d = i & 31;
        const float* qp = qkv + (size_t)(rbase + m) * ldq + h * HDIM + d;
        Kt[d * KT_STRIDE + m] = qp[CDIM];
        Vt[d * KT_STRIDE + m] = qp[2 * CDIM];
    }
    for (int i = tid; i < NTOK; i += 256)
        lab[i] = shifted ? labels[(w & 7) * NTOK + i] : 0;
    __syncthreads();

    int warp = tid >> 5, lane = tid & 31;
    const float scale = 0.17677669529663689f;  // 32^-0.5

    for (int n = warp; n < NTOK; n += 8) {
        float qreg = qkv[(size_t)(rbase + n) * ldq + h * HDIM + lane] * scale;
        float qv[32];
        #pragma unroll
        for (int d = 0; d < 32; d++) qv[d] = __shfl_sync(0xffffffffu, qreg, d);
        int labn = lab[n];
        const float* bp = biasT + ((size_t)h * NTOK + n) * NTOK;

        float s[16];
        float mx = -1e30f;
        #pragma unroll
        for (int j = 0; j < 4; j++) {
            int m0 = 4 * (lane + 32 * j);
            float4 a = make_float4(-1e30f, -1e30f, -1e30f, -1e30f);
            if (m0 < NTOK) {
                a = make_float4(0.f, 0.f, 0.f, 0.f);
                #pragma unroll
                for (int d = 0; d < 32; d++) {
                    float4 k4 = *(const float4*)&Kt[d * KT_STRIDE + m0];
                    float q = qv[d];
                    a.x += q * k4.x; a.y += q * k4.y; a.z += q * k4.z; a.w += q * k4.w;
                }
                float4 b4 = *(const float4*)(bp + m0);
                a.x += b4.x; a.y += b4.y; a.z += b4.z; a.w += b4.w;
                if (shifted) {
                    a.x += (lab[m0]     != labn) ? -100.f : 0.f;
                    a.y += (lab[m0 + 1] != labn) ? -100.f : 0.f;
                    a.z += (lab[m0 + 2] != labn) ? -100.f : 0.f;
                    a.w += (lab[m0 + 3] != labn) ? -100.f : 0.f;
                }
            }
            s[4 * j] = a.x; s[4 * j + 1] = a.y; s[4 * j + 2] = a.z; s[4 * j + 3] = a.w;
            mx = fmaxf(mx, fmaxf(fmaxf(a.x, a.y), fmaxf(a.z, a.w)));
        }
        #pragma unroll
        for (int o = 16; o; o >>= 1) mx = fmaxf(mx, __shfl_xor_sync(0xffffffffu, mx, o));

        float sum = 0.f;
        #pragma unroll
        for (int t = 0; t < 16; t++) { float e = __expf(s[t] - mx); s[t] = e; sum += e; }
        #pragma unroll
        for (int o = 16; o; o >>= 1) sum += __shfl_xor_sync(0xffffffffu, sum, o);

        float acc[32];
        #pragma unroll
        for (int d = 0; d < 32; d++) acc[d] = 0.f;
        #pragma unroll
        for (int j = 0; j < 4; j++) {
            int m0 = 4 * (lane + 32 * j);
            if (m0 < NTOK) {
                float e0 = s[4*j], e1 = s[4*j+1], e2 = s[4*j+2], e3 = s[4*j+3];
                #pragma unroll
                for (int d = 0; d < 32; d++) {
                    float4 v4 = *(const float4*)&Vt[d * KT_STRIDE + m0];
                    acc[d] += e0 * v4.x + e1 * v4.y + e2 * v4.z + e3 * v4.w;
                }
            }
        }
        #pragma unroll
        for (int o = 16; o; o >>= 1)
            #pragma unroll
            for (int d = 0; d < 32; d++)
                acc[d] += __shfl_xor_sync(0xffffffffu, acc[d], o);
        float ov = 0.f;
        #pragma unroll
        for (int d = 0; d < 32; d++) ov = (lane == d) ? acc[d] : ov;
        out[(size_t)(rbase + n) * CDIM + h * HDIM + lane] = ov / sum;
    }
}

// ---------------------------------------------------------------------------
// Head: conv2 (64->2 1x1) + gelu ; final branch product
// ---------------------------------------------------------------------------
__global__ void c2_kernel(const float* __restrict__ t1, const float* __restrict__ w,
                          const float* __restrict__ b, float* __restrict__ out) {
    int idx = blockIdx.x * blockDim.x + threadIdx.x;
    if (idx >= NTOKTOT * 2) return;
    int t = idx >> 1, p = idx & 1;
    const float* row = t1 + (size_t)t * 64;
    const float* wp = w + p * 64;
    float s = b[p];
    #pragma unroll
    for (int k = 0; k < 64; k++) s += row[k] * wp[k];
    out[idx] = gelu_f(s);
}

__global__ void final_mul_kernel(const float* __restrict__ o2, float* __restrict__ out) {
    int i = blockIdx.x * blockDim.x + threadIdx.x;
    if (i >= NB * 2 * SPAT) return;
    int b = i / (2 * SPAT);
    int rem = i % (2 * SPAT);
    int p = rem / SPAT;
    int sp = rem % SPAT;
    int t = b * SPAT + sp;
    out[i] = o2[t * 2 + p] * o2[2 * NTOKTOT + t * 2 + p];
}

// ---------------------------------------------------------------------------
// Host orchestration
// ---------------------------------------------------------------------------
extern "C" void kernel_launch(void* const* d_in, const int* in_sizes, int n_in,
                              void* d_out, int out_size) {
    (void)in_sizes; (void)n_in; (void)out_size;
    const float* x      = (const float*)d_in[0];
    const float* n1_g   = (const float*)d_in[1];
    const float* n1_b   = (const float*)d_in[2];
    const float* qkv_w  = (const float*)d_in[3];
    const float* qkv_b  = (const float*)d_in[4];
    const float* proj_w = (const float*)d_in[5];
    const float* proj_b = (const float*)d_in[6];
    const float* rpb    = (const float*)d_in[7];
    const float* n2_g   = (const float*)d_in[8];
    const float* n2_b   = (const float*)d_in[9];
    const float* fc1_w  = (const float*)d_in[10];
    const float* fc1_b  = (const float*)d_in[11];
    const float* fc2_w  = (const float*)d_in[12];
    const float* fc2_b  = (const float*)d_in[13];
    const float* hln_g  = (const float*)d_in[14];
    const float* hln_b  = (const float*)d_in[15];
    const float* c1_w   = (const float*)d_in[16];
    const float* c1_b   = (const float*)d_in[17];
    const float* c2_w   = (const float*)d_in[18];
    const float* c2_b   = (const float*)d_in[19];
    const int*   rpi    = (const int*)d_in[20];
    float* out = (float*)d_out;

    float *xcur, *bufA, *bufB, *big, *biasbuf, *c1buf, *out2;
    int *map0, *map1, *lab;
    cudaGetSymbolAddress((void**)&xcur,    g_xcur);
    cudaGetSymbolAddress((void**)&bufA,    g_bufA);
    cudaGetSymbolAddress((void**)&bufB,    g_bufB);
    cudaGetSymbolAddress((void**)&big,     g_big);
    cudaGetSymbolAddress((void**)&biasbuf, g_bias);
    cudaGetSymbolAddress((void**)&c1buf,   g_c1);
    cudaGetSymbolAddress((void**)&out2,    g_out2);
    cudaGetSymbolAddress((void**)&map0,    g_map0);
    cudaGetSymbolAddress((void**)&map1,    g_map1);
    cudaGetSymbolAddress((void**)&lab,     g_lab);

    const int ATTN_SMEM = (64 * KT_STRIDE + NTOK) * 4;
    cudaFuncSetAttribute(attn_kernel, cudaFuncAttributeMaxDynamicSharedMemorySize, ATTN_SMEM);

    build_maps_kernel<<<(NTOKTOT + 255) / 256, 256>>>(map0, map1, lab);

    auto gemm = [&](const float* A, const float* W, const float* bias, float* C,
                    int M, int N, int K, int ldC, int gelu, const int* scat, int resid) {
        dim3 grid(N / GBN, M / GBM);
        gemm_kernel<<<grid, 256>>>(A, W, bias, C, M, N, K, ldC, gelu, scat, resid);
    };

    for (int br = 0; br < 2; br++) {
        // x (B,C,D,H,W) -> token-major residual buffer
        {
            dim3 blk(32, 8), grd(SPAT / 32, CDIM / 32, NB);
            transpose_in_kernel<<<grd, blk>>>(x, xcur);
        }
        for (int bl = 0; bl < 2; bl++) {
            int ib = br * 2 + bl;
            int shifted = bl;
            const int* map = shifted ? map1 : map0;

            bias_gather_kernel<<<(NHEADS * BIAS_HN + 255) / 256, 256>>>(
                rpb + (size_t)ib * RPBN * NHEADS, rpi, biasbuf);

            ln_kernel<<<NTOKTOT, 256>>>(xcur, n1_g + ib * CDIM, n1_b + ib * CDIM, bufA, map);

            gemm(bufA, qkv_w + (size_t)ib * QKVC * CDIM, qkv_b + ib * QKVC,
                 big, NTOKTOT, QKVC, CDIM, QKVC, 0, nullptr, 0);

            {
                dim3 grd(NHEADS, NWIN);
                attn_kernel<<<grd, 256, ATTN_SMEM>>>(big, QKVC, biasbuf, lab, bufB, shifted);
            }

            gemm(bufB, proj_w + (size_t)ib * CDIM * CDIM, proj_b + ib * CDIM,
                 xcur, NTOKTOT, CDIM, CDIM, CDIM, 0, map, 1);

            ln_kernel<<<NTOKTOT, 256>>>(xcur, n2_g + ib * CDIM, n2_b + ib * CDIM, bufA, nullptr);

            gemm(bufA, fc1_w + (size_t)ib * MLPC * CDIM, fc1_b + ib * MLPC,
                 big, NTOKTOT, MLPC, CDIM, MLPC, 1, nullptr, 0);

            gemm(big, fc2_w + (size_t)ib * CDIM * MLPC, fc2_b + ib * CDIM,
                 xcur, NTOKTOT, CDIM, MLPC, CDIM, 0, nullptr, 1);
        }
        // head
        ln_kernel<<<NTOKTOT, 256>>>(xcur, hln_g + br * CDIM, hln_b + br * CDIM, bufA, nullptr);
        gemm(bufA, c1_w + (size_t)br * 64 * CDIM, c1_b + br * 64,
             c1buf, NTOKTOT, 64, CDIM, 64, 1, nullptr, 0);
        c2_kernel<<<(NTOKTOT * 2 + 255) / 256, 256>>>(
            c1buf, c2_w + br * 2 * 64, c2_b + br * 2, out2 + (size_t)br * NTOKTOT * 2);
    }
    final_mul_kernel<<<(NB * 2 * SPAT + 255) / 256, 256>>>(out2, out);
}

// round 2
// speedup vs baseline: 1.6768x; 1.6768x over previous
#include <cuda_runtime.h>
#include <cuda_bf16.h>
#include <math.h>

// ---------------------------------------------------------------------------
// Problem constants
// ---------------------------------------------------------------------------
#define NB      2            // batch
#define CDIM    768
#define DD      16
#define HH      14
#define WW      14
#define SPAT    (DD*HH*WW)        // 3136
#define NTOKTOT (NB*SPAT)         // 6272
#define NWIN    16                // total windows (2 batches * 8)
#define NWINB   8                 // windows per batch
#define NTOK    392               // tokens per window (8*7*7)
#define NHEADS  24
#define HDIM    32
#define QKVC    (3*CDIM)          // 2304
#define MLPC    (4*CDIM)          // 3072
#define RPBN    2535
#define BIAS_HN (NTOK*NTOK)       // 153664

// ---------------------------------------------------------------------------
// Static device scratch (no runtime allocation allowed)
// ---------------------------------------------------------------------------
__device__ __align__(128) float g_xcur[NTOKTOT*CDIM];
__device__ __align__(128) float g_bufA[NTOKTOT*CDIM];
__device__ __align__(128) float g_bufB[NTOKTOT*CDIM];
__device__ __align__(128) float g_big [NTOKTOT*MLPC];
__device__ __align__(128) float g_bias[NHEADS*BIAS_HN];
__device__ __align__(128) float g_c1  [NTOKTOT*64];
__device__ __align__(128) float g_out2[2*NTOKTOT*2];
__device__ __align__(128) int   g_map0[NTOKTOT];
__device__ __align__(128) int   g_map1[NTOKTOT];
__device__ __align__(128) int   g_lab [NWINB*NTOK];

__device__ __forceinline__ float gelu_f(float x) {
    return 0.5f * x * (1.0f + erff(x * 0.70710678118654752440f));
}

__device__ __forceinline__ unsigned f2tf(float x) {
    unsigned r;
    asm("cvt.rna.tf32.f32 %0, %1;" : "=r"(r) : "f"(x));
    return r;
}

// ---------------------------------------------------------------------------
// Init: window gather/scatter maps + shift-mask region labels
// ---------------------------------------------------------------------------
__global__ void build_maps_kernel(int* map0, int* map1, int* lab) {
    int r = blockIdx.x * blockDim.x + threadIdx.x;
    if (r < NTOKTOT) {
        int b = r / SPAT, rem = r % SPAT;
        int wi = rem / NTOK, n = rem % NTOK;
        int bd = wi >> 2, bh = (wi >> 1) & 1, bw = wi & 1;
        int wd = n / 49, wh = (n / 7) % 7, ww = n % 7;
        int d = bd * 8 + wd, h = bh * 7 + wh, w = bw * 7 + ww;
        map0[r] = b * SPAT + d * (HH*WW) + h * WW + w;
        int ds = (d + 4) & 15, hs = (h + 3) % 14, ws = (w + 3) % 14;
        map1[r] = b * SPAT + ds * (HH*WW) + hs * WW + ws;
    }
    if (r < NWINB * NTOK) {
        int wi = r / NTOK, n = r % NTOK;
        int bd = wi >> 2, bh = (wi >> 1) & 1, bw = wi & 1;
        int wd = n / 49, wh = (n / 7) % 7, ww = n % 7;
        int d = bd * 8 + wd, h = bh * 7 + wh, w = bw * 7 + ww;
        int cd = d < 8 ? 0 : (d < 12 ? 1 : 2);
        int ch = h < 7 ? 0 : (h < 11 ? 1 : 2);
        int cw = w < 7 ? 0 : (w < 11 ? 1 : 2);
        lab[r] = cd * 9 + ch * 3 + cw;
    }
}

// (B, C, S) -> (B, S, C) tiled transpose
__global__ void transpose_in_kernel(const float* __restrict__ x, float* __restrict__ out) {
    __shared__ float tile[32][33];
    int b  = blockIdx.z;
    int s0 = blockIdx.x * 32, c0 = blockIdx.y * 32;
    int tx = threadIdx.x, ty = threadIdx.y;
    #pragma unroll
    for (int i = 0; i < 32; i += 8) {
        int c = c0 + ty + i, s = s0 + tx;
        if (c < CDIM && s < SPAT)
            tile[ty + i][tx] = x[((size_t)b * CDIM + c) * SPAT + s];
    }
    __syncthreads();
    #pragma unroll
    for (int i = 0; i < 32; i += 8) {
        int s = s0 + ty + i, c = c0 + tx;
        if (s < SPAT && c < CDIM)
            out[((size_t)b * SPAT + s) * CDIM + c] = tile[tx][ty + i];
    }
}

// biasT[h][n][m] = rpb[rpi[n][m]][h]
__global__ void bias_gather_kernel(const float* __restrict__ rpb,
                                   const int* __restrict__ rpi,
                                   float* __restrict__ biasT) {
    int idx = blockIdx.x * blockDim.x + threadIdx.x;
    if (idx >= NHEADS * BIAS_HN) return;
    int h  = idx / BIAS_HN;
    int nm = idx % BIAS_HN;
    biasT[idx] = rpb[rpi[nm] * NHEADS + h];
}

// ---------------------------------------------------------------------------
// LayerNorm (row = one token, 768 channels), optional gather map
// ---------------------------------------------------------------------------
__global__ void __launch_bounds__(256) ln_kernel(const float* __restrict__ in,
                                                 const float* __restrict__ gw,
                                                 const float* __restrict__ gb,
                                                 float* __restrict__ out,
                                                 const int* __restrict__ map) {
    int r = blockIdx.x;
    int src = map ? map[r] : r;
    const float* x = in + (size_t)src * CDIM;
    int t = threadIdx.x;
    float v0 = x[t], v1 = x[t + 256], v2 = x[t + 512];
    __shared__ float red[8];
    __shared__ float stat[2];
    float s = v0 + v1 + v2;
    #pragma unroll
    for (int o = 16; o; o >>= 1) s += __shfl_xor_sync(0xffffffffu, s, o);
    if ((t & 31) == 0) red[t >> 5] = s;
    __syncthreads();
    if (t < 8) {
        float z = red[t];
        z += __shfl_xor_sync(0xffu, z, 4);
        z += __shfl_xor_sync(0xffu, z, 2);
        z += __shfl_xor_sync(0xffu, z, 1);
        if (t == 0) stat[0] = z * (1.0f / CDIM);
    }
    __syncthreads();
    float mu = stat[0];
    float d0 = v0 - mu, d1 = v1 - mu, d2 = v2 - mu;
    s = d0 * d0 + d1 * d1 + d2 * d2;
    #pragma unroll
    for (int o = 16; o; o >>= 1) s += __shfl_xor_sync(0xffffffffu, s, o);
    if ((t & 31) == 0) red[t >> 5] = s;
    __syncthreads();
    if (t < 8) {
        float z = red[t];
        z += __shfl_xor_sync(0xffu, z, 4);
        z += __shfl_xor_sync(0xffu, z, 2);
        z += __shfl_xor_sync(0xffu, z, 1);
        if (t == 0) stat[1] = rsqrtf(z * (1.0f / CDIM) + 1e-5f);
    }
    __syncthreads();
    float inv = stat[1];
    float* o = out + (size_t)r * CDIM;
    o[t]       = d0 * inv * gw[t]       + gb[t];
    o[t + 256] = d1 * inv * gw[t + 256] + gb[t + 256];
    o[t + 512] = d2 * inv * gw[t + 512] + gb[t + 512];
}

// ---------------------------------------------------------------------------
// TF32 tensor-core GEMM: C[m][n] = sum_k A[m][k]*W[n][k] (+bias)(gelu)(resid/scatter)
// BM=128 BN=64 BK=32, 256 threads (8 warps), warp tile 32x32 via mma.m16n8k8
// ---------------------------------------------------------------------------
#define GBM 128
#define GBN 64
#define GBK 32
#define AS_STRIDE 36   // 32 + 4 pad -> conflict-free frag loads
#define BS_STRIDE 36

__global__ void __launch_bounds__(256) gemm_tc_kernel(
    const float* __restrict__ A, const float* __restrict__ W,
    const float* __restrict__ bias, float* __restrict__ C,
    int M, int N, int K, int ldC,
    int act_gelu, const int* __restrict__ scatter, int add_resid)
{
    __shared__ float As[GBM * AS_STRIDE];
    __shared__ float Bs[GBN * BS_STRIDE];
    int tid  = threadIdx.x;
    int warp = tid >> 5, lane = tid & 31;
    int wm = warp & 3;            // 4 warps along M  -> 32 rows each
    int wn = warp >> 2;           // 2 warps along N  -> 32 cols each
    int m0 = blockIdx.y * GBM, n0 = blockIdx.x * GBN;
    int gid = lane >> 2, tig = lane & 3;   // group id / thread-in-group

    const float* Aptr = A + (size_t)m0 * K;
    const float* Wptr = W + (size_t)n0 * K;

    float c[2][4][4];   // [mi][ni][reg]
    #pragma unroll
    for (int mi = 0; mi < 2; mi++)
        #pragma unroll
        for (int ni = 0; ni < 4; ni++)
            #pragma unroll
            for (int r = 0; r < 4; r++) c[mi][ni][r] = 0.0f;

    int ldrow = tid >> 3;             // 0..31
    int ldkc  = (tid & 7) * 4;        // 0..28

    for (int k0 = 0; k0 < K; k0 += GBK) {
        // load A tile: 128 rows x 32 k
        #pragma unroll
        for (int l = 0; l < 4; l++) {
            int row = ldrow + l * 32;
            float4 v = *(const float4*)(Aptr + (size_t)row * K + k0 + ldkc);
            float* dst = &As[row * AS_STRIDE + ldkc];
            dst[0] = __uint_as_float(f2tf(v.x));
            dst[1] = __uint_as_float(f2tf(v.y));
            dst[2] = __uint_as_float(f2tf(v.z));
            dst[3] = __uint_as_float(f2tf(v.w));
        }
        // load B tile: 64 rows(n) x 32 k
        #pragma unroll
        for (int l = 0; l < 2; l++) {
            int row = ldrow + l * 32;
            float4 v = *(const float4*)(Wptr + (size_t)row * K + k0 + ldkc);
            float* dst = &Bs[row * BS_STRIDE + ldkc];
            dst[0] = __uint_as_float(f2tf(v.x));
            dst[1] = __uint_as_float(f2tf(v.y));
            dst[2] = __uint_as_float(f2tf(v.z));
            dst[3] = __uint_as_float(f2tf(v.w));
        }
        __syncthreads();

        #pragma unroll
        for (int ks = 0; ks < GBK; ks += 8) {
            unsigned a[2][4], b[4][2];
            #pragma unroll
            for (int mi = 0; mi < 2; mi++) {
                int r0 = wm * 32 + mi * 16 + gid;
                a[mi][0] = __float_as_uint(As[ r0      * AS_STRIDE + ks + tig]);
                a[mi][1] = __float_as_uint(As[(r0 + 8) * AS_STRIDE + ks + tig]);
                a[mi][2] = __float_as_uint(As[ r0      * AS_STRIDE + ks + 4 + tig]);
                a[mi][3] = __float_as_uint(As[(r0 + 8) * AS_STRIDE + ks + 4 + tig]);
            }
            #pragma unroll
            for (int ni = 0; ni < 4; ni++) {
                int nrow = wn * 32 + ni * 8 + gid;
                b[ni][0] = __float_as_uint(Bs[nrow * BS_STRIDE + ks + tig]);
                b[ni][1] = __float_as_uint(Bs[nrow * BS_STRIDE + ks + 4 + tig]);
            }
            #pragma unroll
            for (int mi = 0; mi < 2; mi++)
                #pragma unroll
                for (int ni = 0; ni < 4; ni++) {
                    asm volatile(
                        "mma.sync.aligned.m16n8k8.row.col.f32.tf32.tf32.f32 "
                        "{%0,%1,%2,%3}, {%4,%5,%6,%7}, {%8,%9}, {%0,%1,%2,%3};"
                        : "+f"(c[mi][ni][0]), "+f"(c[mi][ni][1]),
                          "+f"(c[mi][ni][2]), "+f"(c[mi][ni][3])
                        : "r"(a[mi][0]), "r"(a[mi][1]), "r"(a[mi][2]), "r"(a[mi][3]),
                          "r"(b[ni][0]), "r"(b[ni][1]));
                }
        }
        __syncthreads();
    }

    // epilogue: c[mi][ni][r]: r0/r1 -> row gid, cols 2*tig, 2*tig+1 ; r2/r3 -> row gid+8
    #pragma unroll
    for (int mi = 0; mi < 2; mi++) {
        #pragma unroll
        for (int half = 0; half < 2; half++) {
            int gr = m0 + wm * 32 + mi * 16 + gid + half * 8;
            int tr = scatter ? scatter[gr] : gr;
            float* cp = C + (size_t)tr * ldC;
            #pragma unroll
            for (int ni = 0; ni < 4; ni++) {
                int col = n0 + wn * 32 + ni * 8 + 2 * tig;
                #pragma unroll
                for (int q = 0; q < 2; q++) {
                    float v = c[mi][ni][half * 2 + q] + bias[col + q];
                    if (act_gelu) v = gelu_f(v);
                    if (add_resid) v += cp[col + q];
                    cp[col + q] = v;
                }
            }
        }
    }
}

// ---------------------------------------------------------------------------
// Window attention: one block per (head, window). 256 threads (8 warps).
// ---------------------------------------------------------------------------
#define KT_STRIDE 396

__global__ void __launch_bounds__(256, 1) attn_kernel(
    const float* __restrict__ qkv, int ldq,
    const float* __restrict__ biasT,
    const int* __restrict__ labels,
    float* __restrict__ out, int shifted)
{
    extern __shared__ float sm[];
    float* Kt = sm;
    float* Vt = sm + 32 * KT_STRIDE;
    int*   lab = (int*)(sm + 64 * KT_STRIDE);
    int h = blockIdx.x, w = blockIdx.y;
    int tid = threadIdx.x;
    int rbase = w * NTOK;

    for (int i = tid; i < NTOK * 32; i += 256) {
        int m = i >> 5, d = i & 31;
        const float* qp = qkv + (size_t)(rbase + m) * ldq + h * HDIM + d;
        Kt[d * KT_STRIDE + m] = qp[CDIM];
        Vt[d * KT_STRIDE + m] = qp[2 * CDIM];
    }
    for (int i = tid; i < NTOK; i += 256)
        lab[i] = shifted ? labels[(w & 7) * NTOK + i] : 0;
    __syncthreads();

    int warp = tid >> 5, lane = tid & 31;
    const float scale = 0.17677669529663689f;  // 32^-0.5

    for (int n = warp; n < NTOK; n += 8) {
        float qreg = qkv[(size_t)(rbase + n) * ldq + h * HDIM + lane] * scale;
        float qv[32];
        #pragma unroll
        for (int d = 0; d < 32; d++) qv[d] = __shfl_sync(0xffffffffu, qreg, d);
        int labn = lab[n];
        const float* bp = biasT + ((size_t)h * NTOK + n) * NTOK;

        float s[16];
        float mx = -1e30f;
        #pragma unroll
        for (int j = 0; j < 4; j++) {
            int m0 = 4 * (lane + 32 * j);
            float4 a = make_float4(-1e30f, -1e30f, -1e30f, -1e30f);
            if (m0 < NTOK) {
                a = make_float4(0.f, 0.f, 0.f, 0.f);
                #pragma unroll
                for (int d = 0; d < 32; d++) {
                    float4 k4 = *(const float4*)&Kt[d * KT_STRIDE + m0];
                    float q = qv[d];
                    a.x += q * k4.x; a.y += q * k4.y; a.z += q * k4.z; a.w += q * k4.w;
                }
                float4 b4 = *(const float4*)(bp + m0);
                a.x += b4.x; a.y += b4.y; a.z += b4.z; a.w += b4.w;
                if (shifted) {
                    a.x += (lab[m0]     != labn) ? -100.f : 0.f;
                    a.y += (lab[m0 + 1] != labn) ? -100.f : 0.f;
                    a.z += (lab[m0 + 2] != labn) ? -100.f : 0.f;
                    a.w += (lab[m0 + 3] != labn) ? -100.f : 0.f;
                }
            }
            s[4 * j] = a.x; s[4 * j + 1] = a.y; s[4 * j + 2] = a.z; s[4 * j + 3] = a.w;
            mx = fmaxf(mx, fmaxf(fmaxf(a.x, a.y), fmaxf(a.z, a.w)));
        }
        #pragma unroll
        for (int o = 16; o; o >>= 1) mx = fmaxf(mx, __shfl_xor_sync(0xffffffffu, mx, o));

        float sum = 0.f;
        #pragma unroll
        for (int t = 0; t < 16; t++) { float e = __expf(s[t] - mx); s[t] = e; sum += e; }
        #pragma unroll
        for (int o = 16; o; o >>= 1) sum += __shfl_xor_sync(0xffffffffu, sum, o);

        float acc[32];
        #pragma unroll
        for (int d = 0; d < 32; d++) acc[d] = 0.f;
        #pragma unroll
        for (int j = 0; j < 4; j++) {
            int m0 = 4 * (lane + 32 * j);
            if (m0 < NTOK) {
                float e0 = s[4*j], e1 = s[4*j+1], e2 = s[4*j+2], e3 = s[4*j+3];
                #pragma unroll
                for (int d = 0; d < 32; d++) {
                    float4 v4 = *(const float4*)&Vt[d * KT_STRIDE + m0];
                    acc[d] += e0 * v4.x + e1 * v4.y + e2 * v4.z + e3 * v4.w;
                }
            }
        }
        #pragma unroll
        for (int o = 16; o; o >>= 1)
            #pragma unroll
            for (int d = 0; d < 32; d++)
                acc[d] += __shfl_xor_sync(0xffffffffu, acc[d], o);
        float ov = 0.f;
        #pragma unroll
        for (int d = 0; d < 32; d++) ov = (lane == d) ? acc[d] : ov;
        out[(size_t)(rbase + n) * CDIM + h * HDIM + lane] = ov / sum;
    }
}

// ---------------------------------------------------------------------------
// Head: conv2 (64->2 1x1) + gelu ; final branch product
// ---------------------------------------------------------------------------
__global__ void c2_kernel(const float* __restrict__ t1, const float* __restrict__ w,
                          const float* __restrict__ b, float* __restrict__ out) {
    int idx = blockIdx.x * blockDim.x + threadIdx.x;
    if (idx >= NTOKTOT * 2) return;
    int t = idx >> 1, p = idx & 1;
    const float* row = t1 + (size_t)t * 64;
    const float* wp = w + p * 64;
    float s = b[p];
    #pragma unroll
    for (int k = 0; k < 64; k++) s += row[k] * wp[k];
    out[idx] = gelu_f(s);
}

__global__ void final_mul_kernel(const float* __restrict__ o2, float* __restrict__ out) {
    int i = blockIdx.x * blockDim.x + threadIdx.x;
    if (i >= NB * 2 * SPAT) return;
    int b = i / (2 * SPAT);
    int rem = i % (2 * SPAT);
    int p = rem / SPAT;
    int sp = rem % SPAT;
    int t = b * SPAT + sp;
    out[i] = o2[t * 2 + p] * o2[2 * NTOKTOT + t * 2 + p];
}

// ---------------------------------------------------------------------------
// Host orchestration
// ---------------------------------------------------------------------------
extern "C" void kernel_launch(void* const* d_in, const int* in_sizes, int n_in,
                              void* d_out, int out_size) {
    (void)in_sizes; (void)n_in; (void)out_size;
    const float* x      = (const float*)d_in[0];
    const float* n1_g   = (const float*)d_in[1];
    const float* n1_b   = (const float*)d_in[2];
    const float* qkv_w  = (const float*)d_in[3];
    const float* qkv_b  = (const float*)d_in[4];
    const float* proj_w = (const float*)d_in[5];
    const float* proj_b = (const float*)d_in[6];
    const float* rpb    = (const float*)d_in[7];
    const float* n2_g   = (const float*)d_in[8];
    const float* n2_b   = (const float*)d_in[9];
    const float* fc1_w  = (const float*)d_in[10];
    const float* fc1_b  = (const float*)d_in[11];
    const float* fc2_w  = (const float*)d_in[12];
    const float* fc2_b  = (const float*)d_in[13];
    const float* hln_g  = (const float*)d_in[14];
    const float* hln_b  = (const float*)d_in[15];
    const float* c1_w   = (const float*)d_in[16];
    const float* c1_b   = (const float*)d_in[17];
    const float* c2_w   = (const float*)d_in[18];
    const float* c2_b   = (const float*)d_in[19];
    const int*   rpi    = (const int*)d_in[20];
    float* out = (float*)d_out;

    float *xcur, *bufA, *bufB, *big, *biasbuf, *c1buf, *out2;
    int *map0, *map1, *lab;
    cudaGetSymbolAddress((void**)&xcur,    g_xcur);
    cudaGetSymbolAddress((void**)&bufA,    g_bufA);
    cudaGetSymbolAddress((void**)&bufB,    g_bufB);
    cudaGetSymbolAddress((void**)&big,     g_big);
    cudaGetSymbolAddress((void**)&biasbuf, g_bias);
    cudaGetSymbolAddress((void**)&c1buf,   g_c1);
    cudaGetSymbolAddress((void**)&out2,    g_out2);
    cudaGetSymbolAddress((void**)&map0,    g_map0);
    cudaGetSymbolAddress((void**)&map1,    g_map1);
    cudaGetSymbolAddress((void**)&lab,     g_lab);

    const int ATTN_SMEM = (64 * KT_STRIDE + NTOK) * 4;
    cudaFuncSetAttribute(attn_kernel, cudaFuncAttributeMaxDynamicSharedMemorySize, ATTN_SMEM);

    build_maps_kernel<<<(NTOKTOT + 255) / 256, 256>>>(map0, map1, lab);

    auto gemm = [&](const float* A, const float* W, const float* bias, float* C,
                    int M, int N, int K, int ldC, int gelu, const int* scat, int resid) {
        dim3 grid(N / GBN, M / GBM);
        gemm_tc_kernel<<<grid, 256>>>(A, W, bias, C, M, N, K, ldC, gelu, scat, resid);
    };

    for (int br = 0; br < 2; br++) {
        {
            dim3 blk(32, 8), grd(SPAT / 32, CDIM / 32, NB);
            transpose_in_kernel<<<grd, blk>>>(x, xcur);
        }
        for (int bl = 0; bl < 2; bl++) {
            int ib = br * 2 + bl;
            int shifted = bl;
            const int* map = shifted ? map1 : map0;

            bias_gather_kernel<<<(NHEADS * BIAS_HN + 255) / 256, 256>>>(
                rpb + (size_t)ib * RPBN * NHEADS, rpi, biasbuf);

            ln_kernel<<<NTOKTOT, 256>>>(xcur, n1_g + ib * CDIM, n1_b + ib * CDIM, bufA, map);

            gemm(bufA, qkv_w + (size_t)ib * QKVC * CDIM, qkv_b + ib * QKVC,
                 big, NTOKTOT, QKVC, CDIM, QKVC, 0, nullptr, 0);

            {
                dim3 grd(NHEADS, NWIN);
                attn_kernel<<<grd, 256, ATTN_SMEM>>>(big, QKVC, biasbuf, lab, bufB, shifted);
            }

            gemm(bufB, proj_w + (size_t)ib * CDIM * CDIM, proj_b + ib * CDIM,
                 xcur, NTOKTOT, CDIM, CDIM, CDIM, 0, map, 1);

            ln_kernel<<<NTOKTOT, 256>>>(xcur, n2_g + ib * CDIM, n2_b + ib * CDIM, bufA, nullptr);

            gemm(bufA, fc1_w + (size_t)ib * MLPC * CDIM, fc1_b + ib * MLPC,
                 big, NTOKTOT, MLPC, CDIM, MLPC, 1, nullptr, 0);

            gemm(big, fc2_w + (size_t)ib * CDIM * MLPC, fc2_b + ib * CDIM,
                 xcur, NTOKTOT, CDIM, MLPC, CDIM, 0, nullptr, 1);
        }
        // head
        ln_kernel<<<NTOKTOT, 256>>>(xcur, hln_g + br * CDIM, hln_b + br * CDIM, bufA, nullptr);
        gemm(bufA, c1_w + (size_t)br * 64 * CDIM, c1_b + br * 64,
             c1buf, NTOKTOT, 64, CDIM, 64, 1, nullptr, 0);
        c2_kernel<<<(NTOKTOT * 2 + 255) / 256, 256>>>(
            c1buf, c2_w + br * 2 * 64, c2_b + br * 2, out2 + (size_t)br * NTOKTOT * 2);
    }
    final_mul_kernel<<<(NB * 2 * SPAT + 255) / 256, 256>>>(out2, out);
}

// round 3
// speedup vs baseline: 2.1389x; 1.2756x over previous
#include <cuda_runtime.h>
#include <cuda_bf16.h>
#include <math.h>

// ---------------------------------------------------------------------------
// Problem constants
// ---------------------------------------------------------------------------
#define NB      2
#define CDIM    768
#define DD      16
#define HH      14
#define WW      14
#define SPAT    (DD*HH*WW)        // 3136
#define NTOKTOT (NB*SPAT)         // 6272
#define NWIN    16
#define NWINB   8
#define NTOK    392
#define NHEADS  24
#define HDIM    32
#define QKVC    (3*CDIM)          // 2304
#define MLPC    (4*CDIM)          // 3072
#define RPBN    2535
#define BIAS_HN (NTOK*NTOK)

// ---------------------------------------------------------------------------
// Static device scratch
// ---------------------------------------------------------------------------
__device__ __align__(128) float g_xcur[NTOKTOT*CDIM];
__device__ __align__(128) float g_bufA[NTOKTOT*CDIM];
__device__ __align__(128) float g_bufB[NTOKTOT*CDIM];
__device__ __align__(128) float g_big [NTOKTOT*MLPC];
__device__ __align__(128) float g_bias[NHEADS*BIAS_HN];
__device__ __align__(128) float g_c1  [NTOKTOT*64];
__device__ __align__(128) float g_out2[2*NTOKTOT*2];
__device__ __align__(128) int   g_map0[NTOKTOT];
__device__ __align__(128) int   g_map1[NTOKTOT];
__device__ __align__(128) int   g_lab [NWINB*NTOK];
// pre-rounded (tf32) weights
__device__ __align__(128) float g_wqkv[4*QKVC*CDIM];
__device__ __align__(128) float g_wproj[4*CDIM*CDIM];
__device__ __align__(128) float g_wfc1[4*MLPC*CDIM];
__device__ __align__(128) float g_wfc2[4*CDIM*MLPC];

__device__ __forceinline__ float gelu_f(float x) {
    return 0.5f * x * (1.0f + erff(x * 0.70710678118654752440f));
}

__device__ __forceinline__ float f2tf_f(float x) {
    unsigned r;
    asm("cvt.rna.tf32.f32 %0, %1;" : "=r"(r) : "f"(x));
    return __uint_as_float(r);
}

__device__ __forceinline__ void cp16(unsigned saddr, const float* g) {
    asm volatile("cp.async.ca.shared.global [%0], [%1], 16;" :: "r"(saddr), "l"(g) : "memory");
}

// ---------------------------------------------------------------------------
// Weight pre-rounding to tf32 (once per launch)
// ---------------------------------------------------------------------------
__global__ void round_tf32_kernel(const float* __restrict__ in, float* __restrict__ out, int n4) {
    int i = blockIdx.x * blockDim.x + threadIdx.x;
    for (; i < n4; i += gridDim.x * blockDim.x) {
        float4 v = ((const float4*)in)[i];
        v.x = f2tf_f(v.x); v.y = f2tf_f(v.y); v.z = f2tf_f(v.z); v.w = f2tf_f(v.w);
        ((float4*)out)[i] = v;
    }
}

// ---------------------------------------------------------------------------
// Init: window gather/scatter maps + shift-mask region labels
// ---------------------------------------------------------------------------
__global__ void build_maps_kernel(int* map0, int* map1, int* lab) {
    int r = blockIdx.x * blockDim.x + threadIdx.x;
    if (r < NTOKTOT) {
        int b = r / SPAT, rem = r % SPAT;
        int wi = rem / NTOK, n = rem % NTOK;
        int bd = wi >> 2, bh = (wi >> 1) & 1, bw = wi & 1;
        int wd = n / 49, wh = (n / 7) % 7, ww = n % 7;
        int d = bd * 8 + wd, h = bh * 7 + wh, w = bw * 7 + ww;
        map0[r] = b * SPAT + d * (HH*WW) + h * WW + w;
        int ds = (d + 4) & 15, hs = (h + 3) % 14, ws = (w + 3) % 14;
        map1[r] = b * SPAT + ds * (HH*WW) + hs * WW + ws;
    }
    if (r < NWINB * NTOK) {
        int wi = r / NTOK, n = r % NTOK;
        int bd = wi >> 2, bh = (wi >> 1) & 1, bw = wi & 1;
        int wd = n / 49, wh = (n / 7) % 7, ww = n % 7;
        int d = bd * 8 + wd, h = bh * 7 + wh, w = bw * 7 + ww;
        int cd = d < 8 ? 0 : (d < 12 ? 1 : 2);
        int ch = h < 7 ? 0 : (h < 11 ? 1 : 2);
        int cw = w < 7 ? 0 : (w < 11 ? 1 : 2);
        lab[r] = cd * 9 + ch * 3 + cw;
    }
}

// (B, C, S) -> (B, S, C)
__global__ void transpose_in_kernel(const float* __restrict__ x, float* __restrict__ out) {
    __shared__ float tile[32][33];
    int b  = blockIdx.z;
    int s0 = blockIdx.x * 32, c0 = blockIdx.y * 32;
    int tx = threadIdx.x, ty = threadIdx.y;
    #pragma unroll
    for (int i = 0; i < 32; i += 8) {
        int c = c0 + ty + i, s = s0 + tx;
        if (c < CDIM && s < SPAT)
            tile[ty + i][tx] = x[((size_t)b * CDIM + c) * SPAT + s];
    }
    __syncthreads();
    #pragma unroll
    for (int i = 0; i < 32; i += 8) {
        int s = s0 + ty + i, c = c0 + tx;
        if (s < SPAT && c < CDIM)
            out[((size_t)b * SPAT + s) * CDIM + c] = tile[tx][ty + i];
    }
}

__global__ void bias_gather_kernel(const float* __restrict__ rpb,
                                   const int* __restrict__ rpi,
                                   float* __restrict__ biasT) {
    int idx = blockIdx.x * blockDim.x + threadIdx.x;
    if (idx >= NHEADS * BIAS_HN) return;
    int h  = idx / BIAS_HN;
    int nm = idx % BIAS_HN;
    biasT[idx] = rpb[rpi[nm] * NHEADS + h];
}

// ---------------------------------------------------------------------------
// LayerNorm, outputs tf32-rounded (all LN outputs feed GEMM A operands)
// ---------------------------------------------------------------------------
__global__ void __launch_bounds__(256) ln_kernel(const float* __restrict__ in,
                                                 const float* __restrict__ gw,
                                                 const float* __restrict__ gb,
                                                 float* __restrict__ out,
                                                 const int* __restrict__ map) {
    int r = blockIdx.x;
    int src = map ? map[r] : r;
    const float* x = in + (size_t)src * CDIM;
    int t = threadIdx.x;
    float v0 = x[t], v1 = x[t + 256], v2 = x[t + 512];
    __shared__ float red[8];
    __shared__ float stat[2];
    float s = v0 + v1 + v2;
    #pragma unroll
    for (int o = 16; o; o >>= 1) s += __shfl_xor_sync(0xffffffffu, s, o);
    if ((t & 31) == 0) red[t >> 5] = s;
    __syncthreads();
    if (t < 8) {
        float z = red[t];
        z += __shfl_xor_sync(0xffu, z, 4);
        z += __shfl_xor_sync(0xffu, z, 2);
        z += __shfl_xor_sync(0xffu, z, 1);
        if (t == 0) stat[0] = z * (1.0f / CDIM);
    }
    __syncthreads();
    float mu = stat[0];
    float d0 = v0 - mu, d1 = v1 - mu, d2 = v2 - mu;
    s = d0 * d0 + d1 * d1 + d2 * d2;
    #pragma unroll
    for (int o = 16; o; o >>= 1) s += __shfl_xor_sync(0xffffffffu, s, o);
    if ((t & 31) == 0) red[t >> 5] = s;
    __syncthreads();
    if (t < 8) {
        float z = red[t];
        z += __shfl_xor_sync(0xffu, z, 4);
        z += __shfl_xor_sync(0xffu, z, 2);
        z += __shfl_xor_sync(0xffu, z, 1);
        if (t == 0) stat[1] = rsqrtf(z * (1.0f / CDIM) + 1e-5f);
    }
    __syncthreads();
    float inv = stat[1];
    float* o = out + (size_t)r * CDIM;
    o[t]       = f2tf_f(d0 * inv * gw[t]       + gb[t]);
    o[t + 256] = f2tf_f(d1 * inv * gw[t + 256] + gb[t + 256]);
    o[t + 512] = f2tf_f(d2 * inv * gw[t + 512] + gb[t + 512]);
}

// ---------------------------------------------------------------------------
// Pipelined TF32 tensor-core GEMM: BM=128 BN=128 BK=32, 256 thr, 8 warps (2Mx4N)
// warp tile 64x32, mma.m16n8k8, ldmatrix fragment loads, cp.async double buffer.
// Inputs A and W must be pre-rounded to tf32 values.
// ---------------------------------------------------------------------------
#define T2_ASZ (128*36)   // one stage of A (or B) in floats

__global__ void __launch_bounds__(256) gemm_tc2_kernel(
    const float* __restrict__ A, const float* __restrict__ W,
    const float* __restrict__ bias, float* __restrict__ C,
    int M, int N, int K, int ldC,
    int act_gelu, const int* __restrict__ scatter, int add_resid, int round_out)
{
    extern __shared__ float sm2[];
    unsigned sbase = (unsigned)__cvta_generic_to_shared(sm2);
    int tid  = threadIdx.x;
    int warp = tid >> 5, lane = tid & 31;
    int wm = warp >> 2, wn = warp & 3;          // 2 x 4 warps
    int gid = lane >> 2, tig = lane & 3;
    int m0 = blockIdx.y * 128, n0 = blockIdx.x * 128;

    const float* Aptr = A + (size_t)m0 * K;
    const float* Wptr = W + (size_t)n0 * K;

    int ldrow = tid >> 3;             // 0..31
    int ldkc  = (tid & 7) * 4;        // 0..28

    // ldmatrix per-lane address components
    int arow = ((lane >> 3) & 1) * 8 + (lane & 7);
    int acol = (lane >> 4) * 4;
    int brow = (lane >> 4) * 8 + (lane & 7);
    int bcol = ((lane >> 3) & 1) * 4;

    float acc[4][4][4];
    #pragma unroll
    for (int mi = 0; mi < 4; mi++)
        #pragma unroll
        for (int nj = 0; nj < 4; nj++)
            #pragma unroll
            for (int r = 0; r < 4; r++) acc[mi][nj][r] = 0.0f;

    int NT = K >> 5;

    // prologue: stage 0
    {
        const float* ga = Aptr;
        const float* gb = Wptr;
        #pragma unroll
        for (int l = 0; l < 4; l++) {
            int row = ldrow + l * 32;
            cp16(sbase + ((row * 36 + ldkc) << 2), ga + (size_t)row * K + ldkc);
        }
        #pragma unroll
        for (int l = 0; l < 4; l++) {
            int row = ldrow + l * 32;
            cp16(sbase + ((2 * T2_ASZ + row * 36 + ldkc) << 2), gb + (size_t)row * K + ldkc);
        }
        asm volatile("cp.async.commit_group;" ::: "memory");
    }

    for (int t = 0; t < NT; t++) {
        asm volatile("cp.async.wait_group 0;" ::: "memory");
        __syncthreads();
        if (t + 1 < NT) {
            int buf = (t + 1) & 1;
            const float* ga = Aptr + (t + 1) * 32;
            const float* gb = Wptr + (t + 1) * 32;
            #pragma unroll
            for (int l = 0; l < 4; l++) {
                int row = ldrow + l * 32;
                cp16(sbase + ((buf * T2_ASZ + row * 36 + ldkc) << 2), ga + (size_t)row * K + ldkc);
            }
            #pragma unroll
            for (int l = 0; l < 4; l++) {
                int row = ldrow + l * 32;
                cp16(sbase + ((2 * T2_ASZ + buf * T2_ASZ + row * 36 + ldkc) << 2), gb + (size_t)row * K + ldkc);
            }
            asm volatile("cp.async.commit_group;" ::: "memory");
        }
        int sA = (t & 1) * T2_ASZ;
        int sB = 2 * T2_ASZ + (t & 1) * T2_ASZ;
        #pragma unroll
        for (int ks = 0; ks < 32; ks += 8) {
            unsigned af[4][4], bf[4][2];
            #pragma unroll
            for (int mi = 0; mi < 4; mi++) {
                unsigned ad = sbase + ((sA + (wm * 64 + mi * 16 + arow) * 36 + ks + acol) << 2);
                asm volatile("ldmatrix.sync.aligned.m8n8.x4.shared.b16 {%0,%1,%2,%3}, [%4];"
                             : "=r"(af[mi][0]), "=r"(af[mi][1]), "=r"(af[mi][2]), "=r"(af[mi][3])
                             : "r"(ad));
            }
            #pragma unroll
            for (int np = 0; np < 2; np++) {
                unsigned bd = sbase + ((sB + (wn * 32 + np * 16 + brow) * 36 + ks + bcol) << 2);
                asm volatile("ldmatrix.sync.aligned.m8n8.x4.shared.b16 {%0,%1,%2,%3}, [%4];"
                             : "=r"(bf[2*np][0]), "=r"(bf[2*np][1]),
                               "=r"(bf[2*np+1][0]), "=r"(bf[2*np+1][1])
                             : "r"(bd));
            }
            #pragma unroll
            for (int mi = 0; mi < 4; mi++)
                #pragma unroll
                for (int nj = 0; nj < 4; nj++) {
                    asm volatile(
                        "mma.sync.aligned.m16n8k8.row.col.f32.tf32.tf32.f32 "
                        "{%0,%1,%2,%3}, {%4,%5,%6,%7}, {%8,%9}, {%0,%1,%2,%3};"
                        : "+f"(acc[mi][nj][0]), "+f"(acc[mi][nj][1]),
                          "+f"(acc[mi][nj][2]), "+f"(acc[mi][nj][3])
                        : "r"(af[mi][0]), "r"(af[mi][1]), "r"(af[mi][2]), "r"(af[mi][3]),
                          "r"(bf[nj][0]), "r"(bf[nj][1]));
                }
        }
    }

    // epilogue
    float bs0[4], bs1[4];
    #pragma unroll
    for (int nj = 0; nj < 4; nj++) {
        int col = n0 + wn * 32 + nj * 8 + 2 * tig;
        bs0[nj] = bias[col];
        bs1[nj] = bias[col + 1];
    }
    #pragma unroll
    for (int mi = 0; mi < 4; mi++) {
        #pragma unroll
        for (int half = 0; half < 2; half++) {
            int gr = m0 + wm * 64 + mi * 16 + gid + half * 8;
            int tr = scatter ? scatter[gr] : gr;
            float* cp = C + (size_t)tr * ldC;
            #pragma unroll
            for (int nj = 0; nj < 4; nj++) {
                int col = n0 + wn * 32 + nj * 8 + 2 * tig;
                float v0 = acc[mi][nj][half * 2 + 0] + bs0[nj];
                float v1 = acc[mi][nj][half * 2 + 1] + bs1[nj];
                if (act_gelu) { v0 = gelu_f(v0); v1 = gelu_f(v1); }
                if (round_out) { v0 = f2tf_f(v0); v1 = f2tf_f(v1); }
                if (add_resid) { v0 += cp[col]; v1 += cp[col + 1]; }
                cp[col]     = v0;
                cp[col + 1] = v1;
            }
        }
    }
}

// ---------------------------------------------------------------------------
// Small GEMM (kept for the N=64 head conv): fp32 SIMT with in-loop tf32 cvt
// ---------------------------------------------------------------------------
#define GBM 128
#define GBN 64
#define GBK 16
#define A_STRIDE 132
#define B_STRIDE 68

__global__ void __launch_bounds__(256) gemm_small_kernel(
    const float* __restrict__ A, const float* __restrict__ W,
    const float* __restrict__ bias, float* __restrict__ C,
    int M, int N, int K, int ldC, int act_gelu)
{
    __shared__ float As[GBK * A_STRIDE];
    __shared__ float Bs[GBK * B_STRIDE];
    int tid = threadIdx.x;
    int tx = tid & 15, ty = tid >> 4;
    int m0 = blockIdx.y * GBM, n0 = blockIdx.x * GBN;
    const float* Aptr = A + (size_t)m0 * K;
    const float* Wptr = W + (size_t)n0 * K;
    float acc[8][4];
    #pragma unroll
    for (int i = 0; i < 8; i++)
        #pragma unroll
        for (int j = 0; j < 4; j++) acc[i][j] = 0.0f;

    for (int k0 = 0; k0 < K; k0 += GBK) {
        #pragma unroll
        for (int l = 0; l < 2; l++) {
            int f = tid + l * 256;
            int row = f >> 2, kc = (f & 3) * 4;
            float4 v = *(const float4*)(Aptr + (size_t)row * K + k0 + kc);
            As[(kc + 0) * A_STRIDE + row] = v.x;
            As[(kc + 1) * A_STRIDE + row] = v.y;
            As[(kc + 2) * A_STRIDE + row] = v.z;
            As[(kc + 3) * A_STRIDE + row] = v.w;
        }
        {
            int row = tid >> 2, kc = (tid & 3) * 4;
            float4 v = *(const float4*)(Wptr + (size_t)row * K + k0 + kc);
            Bs[(kc + 0) * B_STRIDE + row] = v.x;
            Bs[(kc + 1) * B_STRIDE + row] = v.y;
            Bs[(kc + 2) * B_STRIDE + row] = v.z;
            Bs[(kc + 3) * B_STRIDE + row] = v.w;
        }
        __syncthreads();
        #pragma unroll
        for (int kk = 0; kk < GBK; kk++) {
            float4 a0 = *(const float4*)&As[kk * A_STRIDE + ty * 8];
            float4 a1 = *(const float4*)&As[kk * A_STRIDE + ty * 8 + 4];
            float4 bb = *(const float4*)&Bs[kk * B_STRIDE + tx * 4];
            float a[8] = {a0.x, a0.y, a0.z, a0.w, a1.x, a1.y, a1.z, a1.w};
            float b[4] = {bb.x, bb.y, bb.z, bb.w};
            #pragma unroll
            for (int i = 0; i < 8; i++)
                #pragma unroll
                for (int j = 0; j < 4; j++)
                    acc[i][j] += a[i] * b[j];
        }
        __syncthreads();
    }
    #pragma unroll
    for (int i = 0; i < 8; i++) {
        int gr = m0 + ty * 8 + i;
        float* cp = C + (size_t)gr * ldC + n0 + tx * 4;
        #pragma unroll
        for (int j = 0; j < 4; j++) {
            float v = acc[i][j] + bias[n0 + tx * 4 + j];
            if (act_gelu) v = gelu_f(v);
            cp[j] = v;
        }
    }
}

// ---------------------------------------------------------------------------
// Window attention: one block per (head, window). Output tf32-rounded.
// ---------------------------------------------------------------------------
#define KT_STRIDE 396

__global__ void __launch_bounds__(256, 1) attn_kernel(
    const float* __restrict__ qkv, int ldq,
    const float* __restrict__ biasT,
    const int* __restrict__ labels,
    float* __restrict__ out, int shifted)
{
    extern __shared__ float sm[];
    float* Kt = sm;
    float* Vt = sm + 32 * KT_STRIDE;
    int*   lab = (int*)(sm + 64 * KT_STRIDE);
    int h = blockIdx.x, w = blockIdx.y;
    int tid = threadIdx.x;
    int rbase = w * NTOK;

    for (int i = tid; i < NTOK * 32; i += 256) {
        int m = i >> 5, d = i & 31;
        const float* qp = qkv + (size_t)(rbase + m) * ldq + h * HDIM + d;
        Kt[d * KT_STRIDE + m] = qp[CDIM];
        Vt[d * KT_STRIDE + m] = qp[2 * CDIM];
    }
    for (int i = tid; i < NTOK; i += 256)
        lab[i] = shifted ? labels[(w & 7) * NTOK + i] : 0;
    __syncthreads();

    int warp = tid >> 5, lane = tid & 31;
    const float scale = 0.17677669529663689f;

    for (int n = warp; n < NTOK; n += 8) {
        float qreg = qkv[(size_t)(rbase + n) * ldq + h * HDIM + lane] * scale;
        float qv[32];
        #pragma unroll
        for (int d = 0; d < 32; d++) qv[d] = __shfl_sync(0xffffffffu, qreg, d);
        int labn = lab[n];
        const float* bp = biasT + ((size_t)h * NTOK + n) * NTOK;

        float s[16];
        float mx = -1e30f;
        #pragma unroll
        for (int j = 0; j < 4; j++) {
            int m0 = 4 * (lane + 32 * j);
            float4 a = make_float4(-1e30f, -1e30f, -1e30f, -1e30f);
            if (m0 < NTOK) {
                a = make_float4(0.f, 0.f, 0.f, 0.f);
                #pragma unroll
                for (int d = 0; d < 32; d++) {
                    float4 k4 = *(const float4*)&Kt[d * KT_STRIDE + m0];
                    float q = qv[d];
                    a.x += q * k4.x; a.y += q * k4.y; a.z += q * k4.z; a.w += q * k4.w;
                }
                float4 b4 = *(const float4*)(bp + m0);
                a.x += b4.x; a.y += b4.y; a.z += b4.z; a.w += b4.w;
                if (shifted) {
                    a.x += (lab[m0]     != labn) ? -100.f : 0.f;
                    a.y += (lab[m0 + 1] != labn) ? -100.f : 0.f;
                    a.z += (lab[m0 + 2] != labn) ? -100.f : 0.f;
                    a.w += (lab[m0 + 3] != labn) ? -100.f : 0.f;
                }
            }
            s[4 * j] = a.x; s[4 * j + 1] = a.y; s[4 * j + 2] = a.z; s[4 * j + 3] = a.w;
            mx = fmaxf(mx, fmaxf(fmaxf(a.x, a.y), fmaxf(a.z, a.w)));
        }
        #pragma unroll
        for (int o = 16; o; o >>= 1) mx = fmaxf(mx, __shfl_xor_sync(0xffffffffu, mx, o));

        float sum = 0.f;
        #pragma unroll
        for (int t = 0; t < 16; t++) { float e = __expf(s[t] - mx); s[t] = e; sum += e; }
        #pragma unroll
        for (int o = 16; o; o >>= 1) sum += __shfl_xor_sync(0xffffffffu, sum, o);

        float acc[32];
        #pragma unroll
        for (int d = 0; d < 32; d++) acc[d] = 0.f;
        #pragma unroll
        for (int j = 0; j < 4; j++) {
            int m0 = 4 * (lane + 32 * j);
            if (m0 < NTOK) {
                float e0 = s[4*j], e1 = s[4*j+1], e2 = s[4*j+2], e3 = s[4*j+3];
                #pragma unroll
                for (int d = 0; d < 32; d++) {
                    float4 v4 = *(const float4*)&Vt[d * KT_STRIDE + m0];
                    acc[d] += e0 * v4.x + e1 * v4.y + e2 * v4.z + e3 * v4.w;
                }
            }
        }
        #pragma unroll
        for (int o = 16; o; o >>= 1)
            #pragma unroll
            for (int d = 0; d < 32; d++)
                acc[d] += __shfl_xor_sync(0xffffffffu, acc[d], o);
        float ov = 0.f;
        #pragma unroll
        for (int d = 0; d < 32; d++) ov = (lane == d) ? acc[d] : ov;
        out[(size_t)(rbase + n) * CDIM + h * HDIM + lane] = f2tf_f(ov / sum);
    }
}

// ---------------------------------------------------------------------------
// Head + final product
// ---------------------------------------------------------------------------
__global__ void c2_kernel(const float* __restrict__ t1, const float* __restrict__ w,
                          const float* __restrict__ b, float* __restrict__ out) {
    int idx = blockIdx.x * blockDim.x + threadIdx.x;
    if (idx >= NTOKTOT * 2) return;
    int t = idx >> 1, p = idx & 1;
    const float* row = t1 + (size_t)t * 64;
    const float* wp = w + p * 64;
    float s = b[p];
    #pragma unroll
    for (int k = 0; k < 64; k++) s += row[k] * wp[k];
    out[idx] = gelu_f(s);
}

__global__ void final_mul_kernel(const float* __restrict__ o2, float* __restrict__ out) {
    int i = blockIdx.x * blockDim.x + threadIdx.x;
    if (i >= NB * 2 * SPAT) return;
    int b = i / (2 * SPAT);
    int rem = i % (2 * SPAT);
    int p = rem / SPAT;
    int sp = rem % SPAT;
    int t = b * SPAT + sp;
    out[i] = o2[t * 2 + p] * o2[2 * NTOKTOT + t * 2 + p];
}

// ---------------------------------------------------------------------------
// Host orchestration
// ---------------------------------------------------------------------------
extern "C" void kernel_launch(void* const* d_in, const int* in_sizes, int n_in,
                              void* d_out, int out_size) {
    (void)in_sizes; (void)n_in; (void)out_size;
    const float* x      = (const float*)d_in[0];
    const float* n1_g   = (const float*)d_in[1];
    const float* n1_b   = (const float*)d_in[2];
    const float* qkv_w  = (const float*)d_in[3];
    const float* qkv_b  = (const float*)d_in[4];
    const float* proj_w = (const float*)d_in[5];
    const float* proj_b = (const float*)d_in[6];
    const float* rpb    = (const float*)d_in[7];
    const float* n2_g   = (const float*)d_in[8];
    const float* n2_b   = (const float*)d_in[9];
    const float* fc1_w  = (const float*)d_in[10];
    const float* fc1_b  = (const float*)d_in[11];
    const float* fc2_w  = (const float*)d_in[12];
    const float* fc2_b  = (const float*)d_in[13];
    const float* hln_g  = (const float*)d_in[14];
    const float* hln_b  = (const float*)d_in[15];
    const float* c1_w   = (const float*)d_in[16];
    const float* c1_b   = (const float*)d_in[17];
    const float* c2_w   = (const float*)d_in[18];
    const float* c2_b   = (const float*)d_in[19];
    const int*   rpi    = (const int*)d_in[20];
    float* out = (float*)d_out;

    float *xcur, *bufA, *bufB, *big, *biasbuf, *c1buf, *out2;
    float *wqkv, *wproj, *wfc1, *wfc2;
    int *map0, *map1, *lab;
    cudaGetSymbolAddress((void**)&xcur,    g_xcur);
    cudaGetSymbolAddress((void**)&bufA,    g_bufA);
    cudaGetSymbolAddress((void**)&bufB,    g_bufB);
    cudaGetSymbolAddress((void**)&big,     g_big);
    cudaGetSymbolAddress((void**)&biasbuf, g_bias);
    cudaGetSymbolAddress((void**)&c1buf,   g_c1);
    cudaGetSymbolAddress((void**)&out2,    g_out2);
    cudaGetSymbolAddress((void**)&map0,    g_map0);
    cudaGetSymbolAddress((void**)&map1,    g_map1);
    cudaGetSymbolAddress((void**)&lab,     g_lab);
    cudaGetSymbolAddress((void**)&wqkv,    g_wqkv);
    cudaGetSymbolAddress((void**)&wproj,   g_wproj);
    cudaGetSymbolAddress((void**)&wfc1,    g_wfc1);
    cudaGetSymbolAddress((void**)&wfc2,    g_wfc2);

    const int ATTN_SMEM = (64 * KT_STRIDE + NTOK) * 4;
    cudaFuncSetAttribute(attn_kernel, cudaFuncAttributeMaxDynamicSharedMemorySize, ATTN_SMEM);
    const int GEMM2_SMEM = 4 * T2_ASZ * 4;   // 73728 B
    cudaFuncSetAttribute(gemm_tc2_kernel, cudaFuncAttributeMaxDynamicSharedMemorySize, GEMM2_SMEM);

    build_maps_kernel<<<(NTOKTOT + 255) / 256, 256>>>(map0, map1, lab);
    round_tf32_kernel<<<1024, 256>>>(qkv_w,  wqkv,  4 * QKVC * CDIM / 4);
    round_tf32_kernel<<<1024, 256>>>(proj_w, wproj, 4 * CDIM * CDIM / 4);
    round_tf32_kernel<<<1024, 256>>>(fc1_w,  wfc1,  4 * MLPC * CDIM / 4);
    round_tf32_kernel<<<1024, 256>>>(fc2_w,  wfc2,  4 * CDIM * MLPC / 4);

    auto gemm2 = [&](const float* A, const float* W, const float* bias, float* C,
                     int M, int N, int K, int ldC, int gelu, const int* scat,
                     int resid, int round_out) {
        dim3 grid(N / 128, M / 128);
        gemm_tc2_kernel<<<grid, 256, GEMM2_SMEM>>>(A, W, bias, C, M, N, K, ldC,
                                                   gelu, scat, resid, round_out);
    };

    for (int br = 0; br < 2; br++) {
        {
            dim3 blk(32, 8), grd(SPAT / 32, CDIM / 32, NB);
            transpose_in_kernel<<<grd, blk>>>(x, xcur);
        }
        for (int bl = 0; bl < 2; bl++) {
            int ib = br * 2 + bl;
            int shifted = bl;
            const int* map = shifted ? map1 : map0;

            bias_gather_kernel<<<(NHEADS * BIAS_HN + 255) / 256, 256>>>(
                rpb + (size_t)ib * RPBN * NHEADS, rpi, biasbuf);

            ln_kernel<<<NTOKTOT, 256>>>(xcur, n1_g + ib * CDIM, n1_b + ib * CDIM, bufA, map);

            gemm2(bufA, wqkv + (size_t)ib * QKVC * CDIM, qkv_b + ib * QKVC,
                  big, NTOKTOT, QKVC, CDIM, QKVC, 0, nullptr, 0, 0);

            {
                dim3 grd(NHEADS, NWIN);
                attn_kernel<<<grd, 256, ATTN_SMEM>>>(big, QKVC, biasbuf, lab, bufB, shifted);
            }

            gemm2(bufB, wproj + (size_t)ib * CDIM * CDIM, proj_b + ib * CDIM,
                  xcur, NTOKTOT, CDIM, CDIM, CDIM, 0, map, 1, 0);

            ln_kernel<<<NTOKTOT, 256>>>(xcur, n2_g + ib * CDIM, n2_b + ib * CDIM, bufA, nullptr);

            gemm2(bufA, wfc1 + (size_t)ib * MLPC * CDIM, fc1_b + ib * MLPC,
                  big, NTOKTOT, MLPC, CDIM, MLPC, 1, nullptr, 0, 1);

            gemm2(big, wfc2 + (size_t)ib * CDIM * MLPC, fc2_b + ib * CDIM,
                  xcur, NTOKTOT, CDIM, MLPC, CDIM, 0, nullptr, 1, 0);
        }
        // head
        ln_kernel<<<NTOKTOT, 256>>>(xcur, hln_g + br * CDIM, hln_b + br * CDIM, bufA, nullptr);
        {
            dim3 grid(1, NTOKTOT / GBM);
            gemm_small_kernel<<<grid, 256>>>(bufA, c1_w + (size_t)br * 64 * CDIM,
                                             c1_b + br * 64, c1buf, NTOKTOT, 64, CDIM, 64, 1);
        }
        c2_kernel<<<(NTOKTOT * 2 + 255) / 256, 256>>>(
            c1buf, c2_w + br * 2 * 64, c2_b + br * 2, out2 + (size_t)br * NTOKTOT * 2);
    }
    final_mul_kernel<<<(NB * 2 * SPAT + 255) / 256, 256>>>(out2, out);
}

// round 5
// speedup vs baseline: 2.3916x; 1.1182x over previous
#include <cuda_runtime.h>
#include <cuda_fp16.h>
#include <math.h>

// ---------------------------------------------------------------------------
// Problem constants
// ---------------------------------------------------------------------------
#define NB      2
#define CDIM    768
#define DD      16
#define HH      14
#define WW      14
#define SPAT    (DD*HH*WW)        // 3136
#define NTOKTOT (NB*SPAT)         // 6272
#define NWIN    16
#define NWINB   8
#define NTOK    392
#define NHEADS  24
#define HDIM    32
#define QKVC    (3*CDIM)          // 2304
#define MLPC    (4*CDIM)          // 3072
#define RPBN    2535
#define BIAS_HN (NTOK*NTOK)

// ---------------------------------------------------------------------------
// Static device scratch
// ---------------------------------------------------------------------------
__device__ __align__(128) float  g_xcur[NTOKTOT*CDIM];     // fp32 residual stream
__device__ __align__(128) __half g_bufA[NTOKTOT*CDIM];     // LN outputs (GEMM A)
__device__ __align__(128) __half g_bufB[NTOKTOT*CDIM];     // attention outputs
__device__ __align__(128) float  g_qkv [NTOKTOT*QKVC];     // qkv GEMM out (fp32 for attn)
__device__ __align__(128) __half g_bigh[NTOKTOT*MLPC];     // fc1 out (half, fc2 in)
__device__ __align__(128) float  g_bias[NHEADS*BIAS_HN];
__device__ __align__(128) float  g_c1  [NTOKTOT*64];
__device__ __align__(128) float  g_out2[2*NTOKTOT*2];
__device__ __align__(128) int    g_map0[NTOKTOT];
__device__ __align__(128) int    g_map1[NTOKTOT];
__device__ __align__(128) int    g_lab [NWINB*NTOK];
// fp16 weights
__device__ __align__(128) __half g_wqkv[4*QKVC*CDIM];
__device__ __align__(128) __half g_wproj[4*CDIM*CDIM];
__device__ __align__(128) __half g_wfc1[4*MLPC*CDIM];
__device__ __align__(128) __half g_wfc2[4*CDIM*MLPC];

__device__ __forceinline__ float gelu_f(float x) {
    return 0.5f * x * (1.0f + erff(x * 0.70710678118654752440f));
}

__device__ __forceinline__ void cp16(unsigned saddr, const void* g) {
    asm volatile("cp.async.cg.shared.global [%0], [%1], 16;" :: "r"(saddr), "l"(g) : "memory");
}

__device__ __forceinline__ unsigned smem_u32(const void* p) {
    unsigned a;
    asm("{ .reg .u64 t; cvta.to.shared.u64 t, %1; cvt.u32.u64 %0, t; }" : "=r"(a) : "l"(p));
    return a;
}

#define SW128(off) ((off) ^ (((off) >> 3) & 0x70))

// ---------------------------------------------------------------------------
// Weight fp32 -> fp16 (once per launch)
// ---------------------------------------------------------------------------
__global__ void w2h_kernel(const float* __restrict__ in, __half* __restrict__ out, int n4) {
    int i = blockIdx.x * blockDim.x + threadIdx.x;
    for (; i < n4; i += gridDim.x * blockDim.x) {
        float4 v = ((const float4*)in)[i];
        __half2 h0 = __floats2half2_rn(v.x, v.y);
        __half2 h1 = __floats2half2_rn(v.z, v.w);
        ((__half2*)out)[2*i]   = h0;
        ((__half2*)out)[2*i+1] = h1;
    }
}

// ---------------------------------------------------------------------------
// Init: window gather/scatter maps + shift-mask region labels
// ---------------------------------------------------------------------------
__global__ void build_maps_kernel(int* map0, int* map1, int* lab) {
    int r = blockIdx.x * blockDim.x + threadIdx.x;
    if (r < NTOKTOT) {
        int b = r / SPAT, rem = r % SPAT;
        int wi = rem / NTOK, n = rem % NTOK;
        int bd = wi >> 2, bh = (wi >> 1) & 1, bw = wi & 1;
        int wd = n / 49, wh = (n / 7) % 7, ww = n % 7;
        int d = bd * 8 + wd, h = bh * 7 + wh, w = bw * 7 + ww;
        map0[r] = b * SPAT + d * (HH*WW) + h * WW + w;
        int ds = (d + 4) & 15, hs = (h + 3) % 14, ws = (w + 3) % 14;
        map1[r] = b * SPAT + ds * (HH*WW) + hs * WW + ws;
    }
    if (r < NWINB * NTOK) {
        int wi = r / NTOK, n = r % NTOK;
        int bd = wi >> 2, bh = (wi >> 1) & 1, bw = wi & 1;
        int wd = n / 49, wh = (n / 7) % 7, ww = n % 7;
        int d = bd * 8 + wd, h = bh * 7 + wh, w = bw * 7 + ww;
        int cd = d < 8 ? 0 : (d < 12 ? 1 : 2);
        int ch = h < 7 ? 0 : (h < 11 ? 1 : 2);
        int cw = w < 7 ? 0 : (w < 11 ? 1 : 2);
        lab[r] = cd * 9 + ch * 3 + cw;
    }
}

// (B, C, S) -> (B, S, C)
__global__ void transpose_in_kernel(const float* __restrict__ x, float* __restrict__ out) {
    __shared__ float tile[32][33];
    int b  = blockIdx.z;
    int s0 = blockIdx.x * 32, c0 = blockIdx.y * 32;
    int tx = threadIdx.x, ty = threadIdx.y;
    #pragma unroll
    for (int i = 0; i < 32; i += 8) {
        int c = c0 + ty + i, s = s0 + tx;
        if (c < CDIM && s < SPAT)
            tile[ty + i][tx] = x[((size_t)b * CDIM + c) * SPAT + s];
    }
    __syncthreads();
    #pragma unroll
    for (int i = 0; i < 32; i += 8) {
        int s = s0 + ty + i, c = c0 + tx;
        if (s < SPAT && c < CDIM)
            out[((size_t)b * SPAT + s) * CDIM + c] = tile[tx][ty + i];
    }
}

__global__ void bias_gather_kernel(const float* __restrict__ rpb,
                                   const int* __restrict__ rpi,
                                   float* __restrict__ biasT) {
    int idx = blockIdx.x * blockDim.x + threadIdx.x;
    if (idx >= NHEADS * BIAS_HN) return;
    int h  = idx / BIAS_HN;
    int nm = idx % BIAS_HN;
    biasT[idx] = rpb[rpi[nm] * NHEADS + h];
}

// ---------------------------------------------------------------------------
// LayerNorm -> half output (optional gather map)
// ---------------------------------------------------------------------------
__global__ void __launch_bounds__(256) ln_kernel(const float* __restrict__ in,
                                                 const float* __restrict__ gw,
                                                 const float* __restrict__ gb,
                                                 __half* __restrict__ out,
                                                 const int* __restrict__ map) {
    int r = blockIdx.x;
    int src = map ? map[r] : r;
    const float* x = in + (size_t)src * CDIM;
    int t = threadIdx.x;
    float v0 = x[t], v1 = x[t + 256], v2 = x[t + 512];
    __shared__ float red[8];
    __shared__ float stat[2];
    float s = v0 + v1 + v2;
    #pragma unroll
    for (int o = 16; o; o >>= 1) s += __shfl_xor_sync(0xffffffffu, s, o);
    if ((t & 31) == 0) red[t >> 5] = s;
    __syncthreads();
    if (t < 8) {
        float z = red[t];
        z += __shfl_xor_sync(0xffu, z, 4);
        z += __shfl_xor_sync(0xffu, z, 2);
        z += __shfl_xor_sync(0xffu, z, 1);
        if (t == 0) stat[0] = z * (1.0f / CDIM);
    }
    __syncthreads();
    float mu = stat[0];
    float d0 = v0 - mu, d1 = v1 - mu, d2 = v2 - mu;
    s = d0 * d0 + d1 * d1 + d2 * d2;
    #pragma unroll
    for (int o = 16; o; o >>= 1) s += __shfl_xor_sync(0xffffffffu, s, o);
    if ((t & 31) == 0) red[t >> 5] = s;
    __syncthreads();
    if (t < 8) {
        float z = red[t];
        z += __shfl_xor_sync(0xffu, z, 4);
        z += __shfl_xor_sync(0xffu, z, 2);
        z += __shfl_xor_sync(0xffu, z, 1);
        if (t == 0) stat[1] = rsqrtf(z * (1.0f / CDIM) + 1e-5f);
    }
    __syncthreads();
    float inv = stat[1];
    __half* o = out + (size_t)r * CDIM;
    o[t]       = __float2half_rn(d0 * inv * gw[t]       + gb[t]);
    o[t + 256] = __float2half_rn(d1 * inv * gw[t + 256] + gb[t + 256]);
    o[t + 512] = __float2half_rn(d2 * inv * gw[t + 512] + gb[t + 512]);
}

// ---------------------------------------------------------------------------
// FP16 tensor-core GEMM: C = A[M,K] * W[N,K]^T (+bias)(gelu)(resid/scatter)
// CTA tile 128x128, BK=64 halves (128B rows, SW128 swizzle), 256 thr, 8 warps
// (2Mx4N), warp tile 64x32, mma.m16n8k16.f16, ldmatrix x4, 3-stage cp.async.
// ---------------------------------------------------------------------------
#define HSTG 16384                      // bytes per matrix per stage
#define HGEMM_SMEM (6 * HSTG)           // 98304 B

__global__ void __launch_bounds__(256) gemm_h_kernel(
    const __half* __restrict__ A, const __half* __restrict__ W,
    const float* __restrict__ bias, void* __restrict__ Cv,
    int M, int N, int K, int ldC,
    int act_gelu, const int* __restrict__ scatter, int add_resid, int out_half)
{
    extern __shared__ __align__(128) char smg[];
    unsigned sbase = smem_u32(smg);
    int tid = threadIdx.x, warp = tid >> 5, lane = tid & 31;
    int wm = warp >> 2, wn = warp & 3;
    int gid = lane >> 2, tig = lane & 3;
    int m0 = blockIdx.y * 128, n0 = blockIdx.x * 128;

    const __half* Ap = A + (size_t)m0 * K;
    const __half* Wp = W + (size_t)n0 * K;
    int NT = K >> 6;

    // cp.async per-thread: 4 chunks A + 4 chunks B per stage
    int ldrow = tid >> 3;        // 0..31
    int ldc   = tid & 7;         // chunk 0..7

    // ldmatrix lane address components
    int l7 = lane & 7;
    int a_row = ((lane >> 3) & 1) * 8 + l7;   // + mi*16 + wm*64
    int a_cs  = lane >> 4;                     // chunk select 0/1
    int b_row = ((lane >> 4) & 1) * 8 + l7;   // + np*16 + wn*32
    int b_cs  = (lane >> 3) & 1;

    float acc[4][4][4];
    #pragma unroll
    for (int mi = 0; mi < 4; mi++)
        #pragma unroll
        for (int nj = 0; nj < 4; nj++)
            #pragma unroll
            for (int r = 0; r < 4; r++) acc[mi][nj][r] = 0.0f;

    // prologue: stages 0,1
    #pragma unroll
    for (int t = 0; t < 2; t++) {
        #pragma unroll
        for (int l = 0; l < 4; l++) {
            int row = ldrow + l * 32;
            unsigned off = SW128((unsigned)(row * 128 + ldc * 16));
            cp16(sbase + t * HSTG + off,          Ap + (size_t)row * K + t * 64 + ldc * 8);
            cp16(sbase + 3*HSTG + t * HSTG + off, Wp + (size_t)row * K + t * 64 + ldc * 8);
        }
        asm volatile("cp.async.commit_group;" ::: "memory");
    }

    for (int t = 0; t < NT; t++) {
        if (t + 1 < NT) asm volatile("cp.async.wait_group 1;" ::: "memory");
        else            asm volatile("cp.async.wait_group 0;" ::: "memory");
        __syncthreads();
        if (t + 2 < NT) {
            int s2 = (t + 2) % 3;
            #pragma unroll
            for (int l = 0; l < 4; l++) {
                int row = ldrow + l * 32;
                unsigned off = SW128((unsigned)(row * 128 + ldc * 16));
                cp16(sbase + s2 * HSTG + off,          Ap + (size_t)row * K + (t+2) * 64 + ldc * 8);
                cp16(sbase + 3*HSTG + s2 * HSTG + off, Wp + (size_t)row * K + (t+2) * 64 + ldc * 8);
            }
            asm volatile("cp.async.commit_group;" ::: "memory");
        }
        unsigned sA = sbase + (t % 3) * HSTG;
        unsigned sB = sbase + 3*HSTG + (t % 3) * HSTG;

        #pragma unroll
        for (int s = 0; s < 4; s++) {            // 4 k16 slices per 64-K tile
            unsigned af[4][4], bf[4][2];
            #pragma unroll
            for (int mi = 0; mi < 4; mi++) {
                int row = wm * 64 + mi * 16 + a_row;
                int ch  = 2 * s + a_cs;
                unsigned ad = sA + SW128((unsigned)(row * 128 + ch * 16));
                asm volatile("ldmatrix.sync.aligned.m8n8.x4.shared.b16 {%0,%1,%2,%3}, [%4];"
                             : "=r"(af[mi][0]), "=r"(af[mi][1]), "=r"(af[mi][2]), "=r"(af[mi][3])
                             : "r"(ad));
            }
            #pragma unroll
            for (int np = 0; np < 2; np++) {
                int row = wn * 32 + np * 16 + b_row;
                int ch  = 2 * s + b_cs;
                unsigned bd = sB + SW128((unsigned)(row * 128 + ch * 16));
                asm volatile("ldmatrix.sync.aligned.m8n8.x4.shared.b16 {%0,%1,%2,%3}, [%4];"
                             : "=r"(bf[2*np][0]), "=r"(bf[2*np][1]),
                               "=r"(bf[2*np+1][0]), "=r"(bf[2*np+1][1])
                             : "r"(bd));
            }
            #pragma unroll
            for (int mi = 0; mi < 4; mi++)
                #pragma unroll
                for (int nj = 0; nj < 4; nj++) {
                    asm volatile(
                        "mma.sync.aligned.m16n8k16.row.col.f32.f16.f16.f32 "
                        "{%0,%1,%2,%3}, {%4,%5,%6,%7}, {%8,%9}, {%0,%1,%2,%3};"
                        : "+f"(acc[mi][nj][0]), "+f"(acc[mi][nj][1]),
                          "+f"(acc[mi][nj][2]), "+f"(acc[mi][nj][3])
                        : "r"(af[mi][0]), "r"(af[mi][1]), "r"(af[mi][2]), "r"(af[mi][3]),
                          "r"(bf[nj][0]), "r"(bf[nj][1]));
                }
        }
        __syncthreads();
    }

    // epilogue
    float bs0[4], bs1[4];
    #pragma unroll
    for (int nj = 0; nj < 4; nj++) {
        int col = n0 + wn * 32 + nj * 8 + 2 * tig;
        bs0[nj] = bias[col];
        bs1[nj] = bias[col + 1];
    }
    #pragma unroll
    for (int mi = 0; mi < 4; mi++) {
        #pragma unroll
        for (int half = 0; half < 2; half++) {
            int gr = m0 + wm * 64 + mi * 16 + gid + half * 8;
            int tr = scatter ? scatter[gr] : gr;
            #pragma unroll
            for (int nj = 0; nj < 4; nj++) {
                int col = n0 + wn * 32 + nj * 8 + 2 * tig;
                float v0 = acc[mi][nj][half * 2 + 0] + bs0[nj];
                float v1 = acc[mi][nj][half * 2 + 1] + bs1[nj];
                if (act_gelu) { v0 = gelu_f(v0); v1 = gelu_f(v1); }
                if (out_half) {
                    __half2* hp = (__half2*)((__half*)Cv + (size_t)tr * ldC + col);
                    *hp = __floats2half2_rn(v0, v1);
                } else {
                    float* cp = (float*)Cv + (size_t)tr * ldC + col;
                    if (add_resid) { v0 += cp[0]; v1 += cp[1]; }
                    cp[0] = v0; cp[1] = v1;
                }
            }
        }
    }
}

// ---------------------------------------------------------------------------
// Small GEMM (head conv, N=64): SIMT, half A, fp32 W
// ---------------------------------------------------------------------------
#define GBM 128
#define GBN 64
#define GBK 16
#define A_STRIDE 132
#define B_STRIDE 68

__global__ void __launch_bounds__(256) gemm_small_kernel(
    const __half* __restrict__ A, const float* __restrict__ W,
    const float* __restrict__ bias, float* __restrict__ C,
    int M, int N, int K, int ldC, int act_gelu)
{
    __shared__ float As[GBK * A_STRIDE];
    __shared__ float Bs[GBK * B_STRIDE];
    int tid = threadIdx.x;
    int tx = tid & 15, ty = tid >> 4;
    int m0 = blockIdx.y * GBM, n0 = blockIdx.x * GBN;
    const __half* Aptr = A + (size_t)m0 * K;
    const float* Wptr = W + (size_t)n0 * K;
    float acc[8][4];
    #pragma unroll
    for (int i = 0; i < 8; i++)
        #pragma unroll
        for (int j = 0; j < 4; j++) acc[i][j] = 0.0f;

    for (int k0 = 0; k0 < K; k0 += GBK) {
        #pragma unroll
        for (int l = 0; l < 2; l++) {
            int f = tid + l * 256;
            int row = f >> 2, kc = (f & 3) * 4;
            const __half* ap = Aptr + (size_t)row * K + k0 + kc;
            __half2 h0 = *(const __half2*)(ap);
            __half2 h1 = *(const __half2*)(ap + 2);
            As[(kc + 0) * A_STRIDE + row] = __low2float(h0);
            As[(kc + 1) * A_STRIDE + row] = __high2float(h0);
            As[(kc + 2) * A_STRIDE + row] = __low2float(h1);
            As[(kc + 3) * A_STRIDE + row] = __high2float(h1);
        }
        {
            int row = tid >> 2, kc = (tid & 3) * 4;
            float4 v = *(const float4*)(Wptr + (size_t)row * K + k0 + kc);
            Bs[(kc + 0) * B_STRIDE + row] = v.x;
            Bs[(kc + 1) * B_STRIDE + row] = v.y;
            Bs[(kc + 2) * B_STRIDE + row] = v.z;
            Bs[(kc + 3) * B_STRIDE + row] = v.w;
        }
        __syncthreads();
        #pragma unroll
        for (int kk = 0; kk < GBK; kk++) {
            float4 a0 = *(const float4*)&As[kk * A_STRIDE + ty * 8];
            float4 a1 = *(const float4*)&As[kk * A_STRIDE + ty * 8 + 4];
            float4 bb = *(const float4*)&Bs[kk * B_STRIDE + tx * 4];
            float a[8] = {a0.x, a0.y, a0.z, a0.w, a1.x, a1.y, a1.z, a1.w};
            float b[4] = {bb.x, bb.y, bb.z, bb.w};
            #pragma unroll
            for (int i = 0; i < 8; i++)
                #pragma unroll
                for (int j = 0; j < 4; j++)
                    acc[i][j] += a[i] * b[j];
        }
        __syncthreads();
    }
    #pragma unroll
    for (int i = 0; i < 8; i++) {
        int gr = m0 + ty * 8 + i;
        float* cp = C + (size_t)gr * ldC + n0 + tx * 4;
        #pragma unroll
        for (int j = 0; j < 4; j++) {
            float v = acc[i][j] + bias[n0 + tx * 4 + j];
            if (act_gelu) v = gelu_f(v);
            cp[j] = v;
        }
    }
}

// ---------------------------------------------------------------------------
// Window attention (SIMT fp32 math, half output)
// ---------------------------------------------------------------------------
#define KT_STRIDE 396

__global__ void __launch_bounds__(256, 1) attn_kernel(
    const float* __restrict__ qkv, int ldq,
    const float* __restrict__ biasT,
    const int* __restrict__ labels,
    __half* __restrict__ out, int shifted)
{
    extern __shared__ float sm[];
    float* Kt = sm;
    float* Vt = sm + 32 * KT_STRIDE;
    int*   lab = (int*)(sm + 64 * KT_STRIDE);
    int h = blockIdx.x, w = blockIdx.y;
    int tid = threadIdx.x;
    int rbase = w * NTOK;

    for (int i = tid; i < NTOK * 32; i += 256) {
        int m = i >> 5, d = i & 31;
        const float* qp = qkv + (size_t)(rbase + m) * ldq + h * HDIM + d;
        Kt[d * KT_STRIDE + m] = qp[CDIM];
        Vt[d * KT_STRIDE + m] = qp[2 * CDIM];
    }
    for (int i = tid; i < NTOK; i += 256)
        lab[i] = shifted ? labels[(w & 7) * NTOK + i] : 0;
    __syncthreads();

    int warp = tid >> 5, lane = tid & 31;
    const float scale = 0.17677669529663689f;

    for (int n = warp; n < NTOK; n += 8) {
        float qreg = qkv[(size_t)(rbase + n) * ldq + h * HDIM + lane] * scale;
        float qv[32];
        #pragma unroll
        for (int d = 0; d < 32; d++) qv[d] = __shfl_sync(0xffffffffu, qreg, d);
        int labn = lab[n];
        const float* bp = biasT + ((size_t)h * NTOK + n) * NTOK;

        float s[16];
        float mx = -1e30f;
        #pragma unroll
        for (int j = 0; j < 4; j++) {
            int m0 = 4 * (lane + 32 * j);
            float4 a = make_float4(-1e30f, -1e30f, -1e30f, -1e30f);
            if (m0 < NTOK) {
                a = make_float4(0.f, 0.f, 0.f, 0.f);
                #pragma unroll
                for (int d = 0; d < 32; d++) {
                    float4 k4 = *(const float4*)&Kt[d * KT_STRIDE + m0];
                    float q = qv[d];
                    a.x += q * k4.x; a.y += q * k4.y; a.z += q * k4.z; a.w += q * k4.w;
                }
                float4 b4 = *(const float4*)(bp + m0);
                a.x += b4.x; a.y += b4.y; a.z += b4.z; a.w += b4.w;
                if (shifted) {
                    a.x += (lab[m0]     != labn) ? -100.f : 0.f;
                    a.y += (lab[m0 + 1] != labn) ? -100.f : 0.f;
                    a.z += (lab[m0 + 2] != labn) ? -100.f : 0.f;
                    a.w += (lab[m0 + 3] != labn) ? -100.f : 0.f;
                }
            }
            s[4 * j] = a.x; s[4 * j + 1] = a.y; s[4 * j + 2] = a.z; s[4 * j + 3] = a.w;
            mx = fmaxf(mx, fmaxf(fmaxf(a.x, a.y), fmaxf(a.z, a.w)));
        }
        #pragma unroll
        for (int o = 16; o; o >>= 1) mx = fmaxf(mx, __shfl_xor_sync(0xffffffffu, mx, o));

        float sum = 0.f;
        #pragma unroll
        for (int t = 0; t < 16; t++) { float e = __expf(s[t] - mx); s[t] = e; sum += e; }
        #pragma unroll
        for (int o = 16; o; o >>= 1) sum += __shfl_xor_sync(0xffffffffu, sum, o);

        float acc[32];
        #pragma unroll
        for (int d = 0; d < 32; d++) acc[d] = 0.f;
        #pragma unroll
        for (int j = 0; j < 4; j++) {
            int m0 = 4 * (lane + 32 * j);
            if (m0 < NTOK) {
                float e0 = s[4*j], e1 = s[4*j+1], e2 = s[4*j+2], e3 = s[4*j+3];
                #pragma unroll
                for (int d = 0; d < 32; d++) {
                    float4 v4 = *(const float4*)&Vt[d * KT_STRIDE + m0];
                    acc[d] += e0 * v4.x + e1 * v4.y + e2 * v4.z + e3 * v4.w;
                }
            }
        }
        #pragma unroll
        for (int o = 16; o; o >>= 1)
            #pragma unroll
            for (int d = 0; d < 32; d++)
                acc[d] += __shfl_xor_sync(0xffffffffu, acc[d], o);
        float ov = 0.f;
        #pragma unroll
        for (int d = 0; d < 32; d++) ov = (lane == d) ? acc[d] : ov;
        out[(size_t)(rbase + n) * CDIM + h * HDIM + lane] = __float2half_rn(ov / sum);
    }
}

// ---------------------------------------------------------------------------
// Head + final product
// ---------------------------------------------------------------------------
__global__ void c2_kernel(const float* __restrict__ t1, const float* __restrict__ w,
                          const float* __restrict__ b, float* __restrict__ out) {
    int idx = blockIdx.x * blockDim.x + threadIdx.x;
    if (idx >= NTOKTOT * 2) return;
    int t = idx >> 1, p = idx & 1;
    const float* row = t1 + (size_t)t * 64;
    const float* wp = w + p * 64;
    float s = b[p];
    #pragma unroll
    for (int k = 0; k < 64; k++) s += row[k] * wp[k];
    out[idx] = gelu_f(s);
}

__global__ void final_mul_kernel(const float* __restrict__ o2, float* __restrict__ out) {
    int i = blockIdx.x * blockDim.x + threadIdx.x;
    if (i >= NB * 2 * SPAT) return;
    int b = i / (2 * SPAT);
    int rem = i % (2 * SPAT);
    int p = rem / SPAT;
    int sp = rem % SPAT;
    int t = b * SPAT + sp;
    out[i] = o2[t * 2 + p] * o2[2 * NTOKTOT + t * 2 + p];
}

// ---------------------------------------------------------------------------
// Host orchestration
// ---------------------------------------------------------------------------
extern "C" void kernel_launch(void* const* d_in, const int* in_sizes, int n_in,
                              void* d_out, int out_size) {
    (void)in_sizes; (void)n_in; (void)out_size;
    const float* x      = (const float*)d_in[0];
    const float* n1_g   = (const float*)d_in[1];
    const float* n1_b   = (const float*)d_in[2];
    const float* qkv_w  = (const float*)d_in[3];
    const float* qkv_b  = (const float*)d_in[4];
    const float* proj_w = (const float*)d_in[5];
    const float* proj_b = (const float*)d_in[6];
    const float* rpb    = (const float*)d_in[7];
    const float* n2_g   = (const float*)d_in[8];
    const float* n2_b   = (const float*)d_in[9];
    const float* fc1_w  = (const float*)d_in[10];
    const float* fc1_b  = (const float*)d_in[11];
    const float* fc2_w  = (const float*)d_in[12];
    const float* fc2_b  = (const float*)d_in[13];
    const float* hln_g  = (const float*)d_in[14];
    const float* hln_b  = (const float*)d_in[15];
    const float* c1_w   = (const float*)d_in[16];
    const float* c1_b   = (const float*)d_in[17];
    const float* c2_w   = (const float*)d_in[18];
    const float* c2_b   = (const float*)d_in[19];
    const int*   rpi    = (const int*)d_in[20];
    float* out = (float*)d_out;

    float *xcur, *qkvbuf, *biasbuf, *c1buf, *out2;
    __half *bufA, *bufB, *bigh, *wqkv, *wproj, *wfc1, *wfc2;
    int *map0, *map1, *lab;
    cudaGetSymbolAddress((void**)&xcur,    g_xcur);
    cudaGetSymbolAddress((void**)&bufA,    g_bufA);
    cudaGetSymbolAddress((void**)&bufB,    g_bufB);
    cudaGetSymbolAddress((void**)&qkvbuf,  g_qkv);
    cudaGetSymbolAddress((void**)&bigh,    g_bigh);
    cudaGetSymbolAddress((void**)&biasbuf, g_bias);
    cudaGetSymbolAddress((void**)&c1buf,   g_c1);
    cudaGetSymbolAddress((void**)&out2,    g_out2);
    cudaGetSymbolAddress((void**)&map0,    g_map0);
    cudaGetSymbolAddress((void**)&map1,    g_map1);
    cudaGetSymbolAddress((void**)&lab,     g_lab);
    cudaGetSymbolAddress((void**)&wqkv,    g_wqkv);
    cudaGetSymbolAddress((void**)&wproj,   g_wproj);
    cudaGetSymbolAddress((void**)&wfc1,    g_wfc1);
    cudaGetSymbolAddress((void**)&wfc2,    g_wfc2);

    const int ATTN_SMEM = (64 * KT_STRIDE + NTOK) * 4;
    cudaFuncSetAttribute(attn_kernel, cudaFuncAttributeMaxDynamicSharedMemorySize, ATTN_SMEM);
    cudaFuncSetAttribute(gemm_h_kernel, cudaFuncAttributeMaxDynamicSharedMemorySize, HGEMM_SMEM);

    build_maps_kernel<<<(NTOKTOT + 255) / 256, 256>>>(map0, map1, lab);
    w2h_kernel<<<1024, 256>>>(qkv_w,  wqkv,  4 * QKVC * CDIM / 4);
    w2h_kernel<<<1024, 256>>>(proj_w, wproj, 4 * CDIM * CDIM / 4);
    w2h_kernel<<<1024, 256>>>(fc1_w,  wfc1,  4 * MLPC * CDIM / 4);
    w2h_kernel<<<1024, 256>>>(fc2_w,  wfc2,  4 * CDIM * MLPC / 4);

    auto gemm = [&](const __half* A, const __half* W, const float* bias, void* C,
                    int M, int N, int K, int ldC, int gelu, const int* scat,
                    int resid, int out_half) {
        dim3 grid(N / 128, M / 128);
        gemm_h_kernel<<<grid, 256, HGEMM_SMEM>>>(A, W, bias, C, M, N, K, ldC,
                                                 gelu, scat, resid, out_half);
    };

    for (int br = 0; br < 2; br++) {
        {
            dim3 blk(32, 8), grd(SPAT / 32, CDIM / 32, NB);
            transpose_in_kernel<<<grd, blk>>>(x, xcur);
        }
        for (int bl = 0; bl < 2; bl++) {
            int ib = br * 2 + bl;
            int shifted = bl;
            const int* map = shifted ? map1 : map0;

            bias_gather_kernel<<<(NHEADS * BIAS_HN + 255) / 256, 256>>>(
                rpb + (size_t)ib * RPBN * NHEADS, rpi, biasbuf);

            ln_kernel<<<NTOKTOT, 256>>>(xcur, n1_g + ib * CDIM, n1_b + ib * CDIM, bufA, map);

            gemm(bufA, wqkv + (size_t)ib * QKVC * CDIM, qkv_b + ib * QKVC,
                 qkvbuf, NTOKTOT, QKVC, CDIM, QKVC, 0, nullptr, 0, 0);

            {
                dim3 grd(NHEADS, NWIN);
                attn_kernel<<<grd, 256, ATTN_SMEM>>>(qkvbuf, QKVC, biasbuf, lab, bufB, shifted);
            }

            gemm(bufB, wproj + (size_t)ib * CDIM * CDIM, proj_b + ib * CDIM,
                 xcur, NTOKTOT, CDIM, CDIM, CDIM, 0, map, 1, 0);

            ln_kernel<<<NTOKTOT, 256>>>(xcur, n2_g + ib * CDIM, n2_b + ib * CDIM, bufA, nullptr);

            gemm(bufA, wfc1 + (size_t)ib * MLPC * CDIM, fc1_b + ib * MLPC,
                 bigh, NTOKTOT, MLPC, CDIM, MLPC, 1, nullptr, 0, 1);

            gemm(bigh, wfc2 + (size_t)ib * CDIM * MLPC, fc2_b + ib * CDIM,
                 xcur, NTOKTOT, CDIM, MLPC, CDIM, 0, nullptr, 1, 0);
        }
        // head
        ln_kernel<<<NTOKTOT, 256>>>(xcur, hln_g + br * CDIM, hln_b + br * CDIM, bufA, nullptr);
        {
            dim3 grid(1, NTOKTOT / GBM);
            gemm_small_kernel<<<grid, 256>>>(bufA, c1_w + (size_t)br * 64 * CDIM,
                                             c1_b + br * 64, c1buf, NTOKTOT, 64, CDIM, 64, 1);
        }
        c2_kernel<<<(NTOKTOT * 2 + 255) / 256, 256>>>(
            c1buf, c2_w + br * 2 * 64, c2_b + br * 2, out2 + (size_t)br * NTOKTOT * 2);
    }
    final_mul_kernel<<<(NB * 2 * SPAT + 255) / 256, 256>>>(out2, out);
}

// round 7
// speedup vs baseline: 5.0393x; 2.1071x over previous
#include <cuda_runtime.h>
#include <cuda_fp16.h>
#include <math.h>

// ---------------------------------------------------------------------------
#define NB      2
#define CDIM    768
#define DD      16
#define HH      14
#define WW      14
#define SPAT    (DD*HH*WW)        // 3136
#define NTOKTOT (NB*SPAT)         // 6272
#define NWIN    16
#define NWINB   8
#define NTOK    392
#define NHEADS  24
#define HDIM    32
#define QKVC    (3*CDIM)          // 2304
#define MLPC    (4*CDIM)          // 3072
#define RPBN    2535
#define BIAS_HN (NTOK*NTOK)

// ---------------------------------------------------------------------------
__device__ __align__(128) float  g_xcur[NTOKTOT*CDIM];
__device__ __align__(128) __half g_bufA[NTOKTOT*CDIM];
__device__ __align__(128) __half g_bufB[NTOKTOT*CDIM];
__device__ __align__(128) __half g_qkvh[NTOKTOT*QKVC];
__device__ __align__(128) __half g_bigh[NTOKTOT*MLPC];
__device__ __align__(128) float  g_bias[NHEADS*BIAS_HN];
__device__ __align__(128) float  g_c1  [NTOKTOT*64];
__device__ __align__(128) float  g_out2[2*NTOKTOT*2];
__device__ __align__(128) int    g_map0[NTOKTOT];
__device__ __align__(128) int    g_map1[NTOKTOT];
__device__ __align__(128) int    g_lab [NWINB*NTOK];
__device__ __align__(128) __half g_wqkv[4*QKVC*CDIM];
__device__ __align__(128) __half g_wproj[4*CDIM*CDIM];
__device__ __align__(128) __half g_wfc1[4*MLPC*CDIM];
__device__ __align__(128) __half g_wfc2[4*CDIM*MLPC];

__device__ __forceinline__ float gelu_f(float x) {
    return 0.5f * x * (1.0f + erff(x * 0.70710678118654752440f));
}

__device__ __forceinline__ unsigned pack_h2(float lo, float hi) {
    unsigned r;
    asm("cvt.rn.f16x2.f32 %0, %1, %2;" : "=r"(r) : "f"(hi), "f"(lo));
    return r;
}

__device__ __forceinline__ void cp16(unsigned saddr, const void* g) {
    asm volatile("cp.async.cg.shared.global [%0], [%1], 16;" :: "r"(saddr), "l"(g) : "memory");
}

__device__ __forceinline__ unsigned smem_u32(const void* p) {
    unsigned a;
    asm("{ .reg .u64 t; cvta.to.shared.u64 t, %1; cvt.u32.u64 %0, t; }" : "=r"(a) : "l"(p));
    return a;
}

#define SW128(off) ((off) ^ (((off) >> 3) & 0x70))

#define LDSM_X4(r0, r1, r2, r3, addr) \
    asm volatile("ldmatrix.sync.aligned.m8n8.x4.shared.b16 {%0,%1,%2,%3}, [%4];" \
                 : "=r"(r0), "=r"(r1), "=r"(r2), "=r"(r3) : "r"(addr))

#define MMA_F16(c, a, b0v, b1v) \
    asm volatile("mma.sync.aligned.m16n8k16.row.col.f32.f16.f16.f32 " \
                 "{%0,%1,%2,%3}, {%4,%5,%6,%7}, {%8,%9}, {%0,%1,%2,%3};" \
                 : "+f"((c)[0]), "+f"((c)[1]), "+f"((c)[2]), "+f"((c)[3]) \
                 : "r"((a)[0]), "r"((a)[1]), "r"((a)[2]), "r"((a)[3]), \
                   "r"(b0v), "r"(b1v))

// ---------------------------------------------------------------------------
__global__ void w2h_kernel(const float* __restrict__ in, __half* __restrict__ out, int n4) {
    int i = blockIdx.x * blockDim.x + threadIdx.x;
    for (; i < n4; i += gridDim.x * blockDim.x) {
        float4 v = ((const float4*)in)[i];
        ((__half2*)out)[2*i]   = __floats2half2_rn(v.x, v.y);
        ((__half2*)out)[2*i+1] = __floats2half2_rn(v.z, v.w);
    }
}

__global__ void build_maps_kernel(int* map0, int* map1, int* lab) {
    int r = blockIdx.x * blockDim.x + threadIdx.x;
    if (r < NTOKTOT) {
        int b = r / SPAT, rem = r % SPAT;
        int wi = rem / NTOK, n = rem % NTOK;
        int bd = wi >> 2, bh = (wi >> 1) & 1, bw = wi & 1;
        int wd = n / 49, wh = (n / 7) % 7, ww = n % 7;
        int d = bd * 8 + wd, h = bh * 7 + wh, w = bw * 7 + ww;
        map0[r] = b * SPAT + d * (HH*WW) + h * WW + w;
        int ds = (d + 4) & 15, hs = (h + 3) % 14, ws = (w + 3) % 14;
        map1[r] = b * SPAT + ds * (HH*WW) + hs * WW + ws;
    }
    if (r < NWINB * NTOK) {
        int wi = r / NTOK, n = r % NTOK;
        int bd = wi >> 2, bh = (wi >> 1) & 1, bw = wi & 1;
        int wd = n / 49, wh = (n / 7) % 7, ww = n % 7;
        int d = bd * 8 + wd, h = bh * 7 + wh, w = bw * 7 + ww;
        int cd = d < 8 ? 0 : (d < 12 ? 1 : 2);
        int ch = h < 7 ? 0 : (h < 11 ? 1 : 2);
        int cw = w < 7 ? 0 : (w < 11 ? 1 : 2);
        lab[r] = cd * 9 + ch * 3 + cw;
    }
}

__global__ void transpose_in_kernel(const float* __restrict__ x, float* __restrict__ out) {
    __shared__ float tile[32][33];
    int b  = blockIdx.z;
    int s0 = blockIdx.x * 32, c0 = blockIdx.y * 32;
    int tx = threadIdx.x, ty = threadIdx.y;
    #pragma unroll
    for (int i = 0; i < 32; i += 8) {
        int c = c0 + ty + i, s = s0 + tx;
        if (c < CDIM && s < SPAT)
            tile[ty + i][tx] = x[((size_t)b * CDIM + c) * SPAT + s];
    }
    __syncthreads();
    #pragma unroll
    for (int i = 0; i < 32; i += 8) {
        int s = s0 + ty + i, c = c0 + tx;
        if (s < SPAT && c < CDIM)
            out[((size_t)b * SPAT + s) * CDIM + c] = tile[tx][ty + i];
    }
}

__global__ void bias_gather_kernel(const float* __restrict__ rpb,
                                   const int* __restrict__ rpi,
                                   float* __restrict__ biasT) {
    int idx = blockIdx.x * blockDim.x + threadIdx.x;
    if (idx >= NHEADS * BIAS_HN) return;
    int h  = idx / BIAS_HN;
    int nm = idx % BIAS_HN;
    biasT[idx] = rpb[rpi[nm] * NHEADS + h];
}

// ---------------------------------------------------------------------------
__global__ void __launch_bounds__(256) ln_kernel(const float* __restrict__ in,
                                                 const float* __restrict__ gw,
                                                 const float* __restrict__ gb,
                                                 __half* __restrict__ out,
                                                 const int* __restrict__ map) {
    int r = blockIdx.x;
    int src = map ? map[r] : r;
    const float* x = in + (size_t)src * CDIM;
    int t = threadIdx.x;
    float v0 = x[t], v1 = x[t + 256], v2 = x[t + 512];
    __shared__ float red[8];
    __shared__ float stat[2];
    float s = v0 + v1 + v2;
    #pragma unroll
    for (int o = 16; o; o >>= 1) s += __shfl_xor_sync(0xffffffffu, s, o);
    if ((t & 31) == 0) red[t >> 5] = s;
    __syncthreads();
    if (t < 8) {
        float z = red[t];
        z += __shfl_xor_sync(0xffu, z, 4);
        z += __shfl_xor_sync(0xffu, z, 2);
        z += __shfl_xor_sync(0xffu, z, 1);
        if (t == 0) stat[0] = z * (1.0f / CDIM);
    }
    __syncthreads();
    float mu = stat[0];
    float d0 = v0 - mu, d1 = v1 - mu, d2 = v2 - mu;
    s = d0 * d0 + d1 * d1 + d2 * d2;
    #pragma unroll
    for (int o = 16; o; o >>= 1) s += __shfl_xor_sync(0xffffffffu, s, o);
    if ((t & 31) == 0) red[t >> 5] = s;
    __syncthreads();
    if (t < 8) {
        float z = red[t];
        z += __shfl_xor_sync(0xffu, z, 4);
        z += __shfl_xor_sync(0xffu, z, 2);
        z += __shfl_xor_sync(0xffu, z, 1);
        if (t == 0) stat[1] = rsqrtf(z * (1.0f / CDIM) + 1e-5f);
    }
    __syncthreads();
    float inv = stat[1];
    __half* o = out + (size_t)r * CDIM;
    o[t]       = __float2half_rn(d0 * inv * gw[t]       + gb[t]);
    o[t + 256] = __float2half_rn(d1 * inv * gw[t + 256] + gb[t + 256]);
    o[t + 512] = __float2half_rn(d2 * inv * gw[t + 512] + gb[t + 512]);
}

// ---------------------------------------------------------------------------
// FP16 GEMM: CTA 128x256, BK=64, warp tile 64x64 (2Mx4N), 3-stage cp.async,
// one sync per tile. SW128 swizzled smem, ldmatrix, mma.m16n8k16 fp32 acc.
// ---------------------------------------------------------------------------
#define HASTG 16384
#define HBSTG 32768
#define HGEMM_SMEM (3*HASTG + 3*HBSTG)   // 147456 B

__global__ void __launch_bounds__(256) gemm_h_kernel(
    const __half* __restrict__ A, const __half* __restrict__ W,
    const float* __restrict__ bias, void* __restrict__ Cv,
    int M, int N, int K, int ldC,
    int act_gelu, const int* __restrict__ scatter, int add_resid, int out_half)
{
    extern __shared__ __align__(128) char smg[];
    unsigned sbase = smem_u32(smg);
    unsigned bbase = sbase + 3 * HASTG;
    int tid = threadIdx.x, warp = tid >> 5, lane = tid & 31;
    int wm = warp >> 2, wn = warp & 3;
    int gid = lane >> 2, tig = lane & 3;
    int m0 = blockIdx.y * 128, n0 = blockIdx.x * 256;

    const __half* Ap = A + (size_t)m0 * K;
    const __half* Wp = W + (size_t)n0 * K;
    int NT = K >> 6;

    int ldrow = tid >> 3;
    int ldc   = tid & 7;

    int l7 = lane & 7;
    int a_row = ((lane >> 3) & 1) * 8 + l7;
    int a_cs  = lane >> 4;
    int b_row = ((lane >> 4) & 1) * 8 + l7;
    int b_cs  = (lane >> 3) & 1;

    float acc[4][8][4];
    #pragma unroll
    for (int mi = 0; mi < 4; mi++)
        #pragma unroll
        for (int nj = 0; nj < 8; nj++)
            #pragma unroll
            for (int r = 0; r < 4; r++) acc[mi][nj][r] = 0.0f;

    #pragma unroll
    for (int t = 0; t < 2; t++) {
        #pragma unroll
        for (int l = 0; l < 4; l++) {
            int row = ldrow + l * 32;
            unsigned off = SW128((unsigned)(row * 128 + ldc * 16));
            cp16(sbase + t * HASTG + off, Ap + (size_t)row * K + t * 64 + ldc * 8);
        }
        #pragma unroll
        for (int l = 0; l < 8; l++) {
            int row = ldrow + l * 32;
            unsigned off = SW128((unsigned)(row * 128 + ldc * 16));
            cp16(bbase + t * HBSTG + off, Wp + (size_t)row * K + t * 64 + ldc * 8);
        }
        asm volatile("cp.async.commit_group;" ::: "memory");
    }

    for (int t = 0; t < NT; t++) {
        if (t + 1 < NT) asm volatile("cp.async.wait_group 1;" ::: "memory");
        else            asm volatile("cp.async.wait_group 0;" ::: "memory");
        __syncthreads();
        if (t + 2 < NT) {
            int s2 = (t + 2) % 3;
            #pragma unroll
            for (int l = 0; l < 4; l++) {
                int row = ldrow + l * 32;
                unsigned off = SW128((unsigned)(row * 128 + ldc * 16));
                cp16(sbase + s2 * HASTG + off, Ap + (size_t)row * K + (t+2) * 64 + ldc * 8);
            }
            #pragma unroll
            for (int l = 0; l < 8; l++) {
                int row = ldrow + l * 32;
                unsigned off = SW128((unsigned)(row * 128 + ldc * 16));
                cp16(bbase + s2 * HBSTG + off, Wp + (size_t)row * K + (t+2) * 64 + ldc * 8);
            }
            asm volatile("cp.async.commit_group;" ::: "memory");
        }
        unsigned sA = sbase + (t % 3) * HASTG;
        unsigned sB = bbase + (t % 3) * HBSTG;

        #pragma unroll
        for (int s = 0; s < 4; s++) {
            unsigned af[4][4], bf[8][2];
            #pragma unroll
            for (int mi = 0; mi < 4; mi++) {
                int row = wm * 64 + mi * 16 + a_row;
                int ch  = 2 * s + a_cs;
                unsigned ad = sA + SW128((unsigned)(row * 128 + ch * 16));
                LDSM_X4(af[mi][0], af[mi][1], af[mi][2], af[mi][3], ad);
            }
            #pragma unroll
            for (int np = 0; np < 4; np++) {
                int row = wn * 64 + np * 16 + b_row;
                int ch  = 2 * s + b_cs;
                unsigned bd = sB + SW128((unsigned)(row * 128 + ch * 16));
                LDSM_X4(bf[2*np][0], bf[2*np][1], bf[2*np+1][0], bf[2*np+1][1], bd);
            }
            #pragma unroll
            for (int mi = 0; mi < 4; mi++)
                #pragma unroll
                for (int nj = 0; nj < 8; nj++)
                    MMA_F16(acc[mi][nj], af[mi], bf[nj][0], bf[nj][1]);
        }
    }

    float bs0[8], bs1[8];
    #pragma unroll
    for (int nj = 0; nj < 8; nj++) {
        int col = n0 + wn * 64 + nj * 8 + 2 * tig;
        bs0[nj] = bias[col];
        bs1[nj] = bias[col + 1];
    }
    #pragma unroll
    for (int mi = 0; mi < 4; mi++) {
        #pragma unroll
        for (int half = 0; half < 2; half++) {
            int gr = m0 + wm * 64 + mi * 16 + gid + half * 8;
            int tr = scatter ? scatter[gr] : gr;
            #pragma unroll
            for (int nj = 0; nj < 8; nj++) {
                int col = n0 + wn * 64 + nj * 8 + 2 * tig;
                float v0 = acc[mi][nj][half * 2 + 0] + bs0[nj];
                float v1 = acc[mi][nj][half * 2 + 1] + bs1[nj];
                if (act_gelu) { v0 = gelu_f(v0); v1 = gelu_f(v1); }
                if (out_half) {
                    unsigned* hp = (unsigned*)((__half*)Cv + (size_t)tr * ldC + col);
                    *hp = pack_h2(v0, v1);
                } else {
                    float* cp = (float*)Cv + (size_t)tr * ldC + col;
                    if (add_resid) { v0 += cp[0]; v1 += cp[1]; }
                    cp[0] = v0; cp[1] = v1;
                }
            }
        }
    }
}

// ---------------------------------------------------------------------------
// Tensor-core window attention. One CTA per (head, window), 256 thr / 8 warps.
// Q,K: 400x40 half (pad), Vt: 32x408 half. FA2 online softmax per m16 tile.
// ---------------------------------------------------------------------------
#define QS_STRIDE 40
#define VT_STRIDE 408
#define ATTN_SMEM_B (400*QS_STRIDE*2*2 + 32*VT_STRIDE*2 + 400*4)

__global__ void __launch_bounds__(256) attn_mma_kernel(
    const __half* __restrict__ qkv,
    const float* __restrict__ biasT,
    const int* __restrict__ labels,
    __half* __restrict__ out, int shifted)
{
    extern __shared__ __align__(16) char smA[];
    __half* Qs = (__half*)smA;
    __half* Ks = Qs + 400 * QS_STRIDE;
    __half* Vt = Ks + 400 * QS_STRIDE;
    int* lab = (int*)(Vt + 32 * VT_STRIDE);
    int h = blockIdx.x, w = blockIdx.y;
    int tid = threadIdx.x;
    int rbase = w * NTOK;

    for (int i = tid; i < (400*QS_STRIDE*2*2 + 32*VT_STRIDE*2) / 16; i += 256)
        ((uint4*)smA)[i] = make_uint4(0, 0, 0, 0);
    __syncthreads();

    for (int i = tid; i < 392 * 4; i += 256) {
        int m = i >> 2, c = i & 3;
        const __half* base = qkv + (size_t)(rbase + m) * QKVC + h * HDIM + c * 8;
        *(uint4*)(Qs + m * QS_STRIDE + c * 8) = *(const uint4*)(base);
        *(uint4*)(Ks + m * QS_STRIDE + c * 8) = *(const uint4*)(base + CDIM);
    }
    for (int m = tid; m < 392; m += 256) {
        const __half* vp = qkv + (size_t)(rbase + m) * QKVC + 2 * CDIM + h * HDIM;
        #pragma unroll
        for (int d = 0; d < 32; d++) Vt[d * VT_STRIDE + m] = vp[d];
    }
    for (int i = tid; i < 400; i += 256)
        lab[i] = (shifted && i < NTOK) ? labels[(w & 7) * NTOK + i] : 0;
    __syncthreads();

    int warp = tid >> 5, lane = tid & 31;
    int gid = lane >> 2, tig = lane & 3;
    int l7 = lane & 7;
    int a_row = ((lane >> 3) & 1) * 8 + l7;
    int a_cs  = lane >> 4;
    int b_row = ((lane >> 4) & 1) * 8 + l7;
    int b_cs  = (lane >> 3) & 1;
    const float scale = 0.17677669529663689f;

    unsigned qsb = smem_u32(Qs);
    unsigned ksb = smem_u32(Ks);
    unsigned vtb = smem_u32(Vt);

    for (int mt = warp; mt < 25; mt += 8) {
        unsigned aq[2][4];
        #pragma unroll
        for (int s = 0; s < 2; s++) {
            unsigned ad = qsb + (unsigned)(((mt * 16 + a_row) * QS_STRIDE + (2*s + a_cs) * 8) * 2);
            LDSM_X4(aq[s][0], aq[s][1], aq[s][2], aq[s][3], ad);
        }
        int q0 = mt * 16 + gid, q1 = q0 + 8;
        int q1ok = (mt != 24);
        int labq0 = lab[q0], labq1 = lab[q1];
        const float* bp0 = biasT + ((size_t)h * NTOK + q0) * NTOK;
        const float* bp1 = q1ok ? biasT + ((size_t)h * NTOK + q1) * NTOK : biasT;

        float mr0 = -1e30f, mr1 = -1e30f, lr0 = 0.f, lr1 = 0.f;
        float acc[4][4];
        #pragma unroll
        for (int j = 0; j < 4; j++)
            #pragma unroll
            for (int r = 0; r < 4; r++) acc[j][r] = 0.f;

        for (int nt = 0; nt < 25; nt++) {
            float c0[4] = {0.f, 0.f, 0.f, 0.f};
            float c1[4] = {0.f, 0.f, 0.f, 0.f};
            #pragma unroll
            for (int s = 0; s < 2; s++) {
                unsigned bd = ksb + (unsigned)(((nt * 16 + b_row) * QS_STRIDE + (2*s + b_cs) * 8) * 2);
                unsigned bf0, bf1, bf2, bf3;
                LDSM_X4(bf0, bf1, bf2, bf3, bd);
                MMA_F16(c0, aq[s], bf0, bf1);
                MMA_F16(c1, aq[s], bf2, bf3);
            }
            float sv[2][4];
            #pragma unroll
            for (int f = 0; f < 2; f++) {
                float* c = f ? c1 : c0;
                int k0 = nt * 16 + f * 8 + 2 * tig;
                int kvalid = !(nt == 24 && f == 1);
                if (kvalid) {
                    float b00 = bp0[k0], b01 = bp0[k0 + 1];
                    float b10 = 0.f, b11 = 0.f;
                    if (q1ok) { b10 = bp1[k0]; b11 = bp1[k0 + 1]; }
                    float mk0 = 0.f, mk1 = 0.f;
                    if (shifted) {
                        int lk0 = lab[k0], lk1 = lab[k0 + 1];
                        mk0 = (lk0 != labq0) ? -100.f : 0.f;
                        mk1 = (lk1 != labq0) ? -100.f : 0.f;
                        b10 += (lk0 != labq1) ? -100.f : 0.f;
                        b11 += (lk1 != labq1) ? -100.f : 0.f;
                    }
                    sv[f][0] = c[0] * scale + b00 + mk0;
                    sv[f][1] = c[1] * scale + b01 + mk1;
                    sv[f][2] = c[2] * scale + b10;
                    sv[f][3] = c[3] * scale + b11;
                } else {
                    sv[f][0] = sv[f][1] = sv[f][2] = sv[f][3] = -1e30f;
                }
            }
            float tm0 = fmaxf(fmaxf(sv[0][0], sv[0][1]), fmaxf(sv[1][0], sv[1][1]));
            float tm1 = fmaxf(fmaxf(sv[0][2], sv[0][3]), fmaxf(sv[1][2], sv[1][3]));
            tm0 = fmaxf(tm0, __shfl_xor_sync(0xffffffffu, tm0, 1));
            tm0 = fmaxf(tm0, __shfl_xor_sync(0xffffffffu, tm0, 2));
            tm1 = fmaxf(tm1, __shfl_xor_sync(0xffffffffu, tm1, 1));
            tm1 = fmaxf(tm1, __shfl_xor_sync(0xffffffffu, tm1, 2));
            float mn0 = fmaxf(mr0, tm0), mn1 = fmaxf(mr1, tm1);
            float al0 = __expf(mr0 - mn0), al1 = __expf(mr1 - mn1);
            float e[2][4];
            #pragma unroll
            for (int f = 0; f < 2; f++) {
                e[f][0] = __expf(sv[f][0] - mn0);
                e[f][1] = __expf(sv[f][1] - mn0);
                e[f][2] = __expf(sv[f][2] - mn1);
                e[f][3] = __expf(sv[f][3] - mn1);
            }
            float ts0 = e[0][0] + e[0][1] + e[1][0] + e[1][1];
            float ts1 = e[0][2] + e[0][3] + e[1][2] + e[1][3];
            ts0 += __shfl_xor_sync(0xffffffffu, ts0, 1);
            ts0 += __shfl_xor_sync(0xffffffffu, ts0, 2);
            ts1 += __shfl_xor_sync(0xffffffffu, ts1, 1);
            ts1 += __shfl_xor_sync(0xffffffffu, ts1, 2);
            lr0 = lr0 * al0 + ts0;
            lr1 = lr1 * al1 + ts1;
            mr0 = mn0; mr1 = mn1;
            #pragma unroll
            for (int j = 0; j < 4; j++) {
                acc[j][0] *= al0; acc[j][1] *= al0;
                acc[j][2] *= al1; acc[j][3] *= al1;
            }
            unsigned pa[4];
            pa[0] = pack_h2(e[0][0], e[0][1]);
            pa[1] = pack_h2(e[0][2], e[0][3]);
            pa[2] = pack_h2(e[1][0], e[1][1]);
            pa[3] = pack_h2(e[1][2], e[1][3]);
            #pragma unroll
            for (int g = 0; g < 2; g++) {
                unsigned bd = vtb + (unsigned)(((g * 16 + b_row) * VT_STRIDE + nt * 16 + b_cs * 8) * 2);
                unsigned bf0, bf1, bf2, bf3;
                LDSM_X4(bf0, bf1, bf2, bf3, bd);
                MMA_F16(acc[2*g],   pa, bf0, bf1);
                MMA_F16(acc[2*g+1], pa, bf2, bf3);
            }
        }
        float li0 = 1.0f / lr0, li1 = 1.0f / lr1;
        if (q0 < NTOK) {
            __half* op = out + (size_t)(rbase + q0) * CDIM + h * HDIM;
            #pragma unroll
            for (int j = 0; j < 4; j++)
                *(unsigned*)(op + j * 8 + 2 * tig) = pack_h2(acc[j][0] * li0, acc[j][1] * li0);
        }
        if (q1ok) {
            __half* op = out + (size_t)(rbase + q1) * CDIM + h * HDIM;
            #pragma unroll
            for (int j = 0; j < 4; j++)
                *(unsigned*)(op + j * 8 + 2 * tig) = pack_h2(acc[j][2] * li1, acc[j][3] * li1);
        }
    }
}

// ---------------------------------------------------------------------------
// Small GEMM (head conv, N=64): SIMT, half A, fp32 W
// ---------------------------------------------------------------------------
#define GBM 128
#define GBK 16
#define A_STRIDE 132
#define B_STRIDE 68

__global__ void __launch_bounds__(256) gemm_small_kernel(
    const __half* __restrict__ A, const float* __restrict__ W,
    const float* __restrict__ bias, float* __restrict__ C,
    int M, int N, int K, int ldC, int act_gelu)
{
    __shared__ float As[GBK * A_STRIDE];
    __shared__ float Bs[GBK * B_STRIDE];
    int tid = threadIdx.x;
    int tx = tid & 15, ty = tid >> 4;
    int m0 = blockIdx.y * GBM, n0 = blockIdx.x * 64;
    const __half* Aptr = A + (size_t)m0 * K;
    const float* Wptr = W + (size_t)n0 * K;
    float acc[8][4];
    #pragma unroll
    for (int i = 0; i < 8; i++)
        #pragma unroll
        for (int j = 0; j < 4; j++) acc[i][j] = 0.0f;

    for (int k0 = 0; k0 < K; k0 += GBK) {
        #pragma unroll
        for (int l = 0; l < 2; l++) {
            int f = tid + l * 256;
            int row = f >> 2, kc = (f & 3) * 4;
            const __half* ap = Aptr + (size_t)row * K + k0 + kc;
            __half2 h0 = *(const __half2*)(ap);
            __half2 h1 = *(const __half2*)(ap + 2);
            As[(kc + 0) * A_STRIDE + row] = __low2float(h0);
            As[(kc + 1) * A_STRIDE + row] = __high2float(h0);
            As[(kc + 2) * A_STRIDE + row] = __low2float(h1);
            As[(kc + 3) * A_STRIDE + row] = __high2float(h1);
        }
        {
            int row = tid >> 2, kc = (tid & 3) * 4;
            float4 v = *(const float4*)(Wptr + (size_t)row * K + k0 + kc);
            Bs[(kc + 0) * B_STRIDE + row] = v.x;
            Bs[(kc + 1) * B_STRIDE + row] = v.y;
            Bs[(kc + 2) * B_STRIDE + row] = v.z;
            Bs[(kc + 3) * B_STRIDE + row] = v.w;
        }
        __syncthreads();
        #pragma unroll
        for (int kk = 0; kk < GBK; kk++) {
            float4 a0 = *(const float4*)&As[kk * A_STRIDE + ty * 8];
            float4 a1 = *(const float4*)&As[kk * A_STRIDE + ty * 8 + 4];
            float4 bb = *(const float4*)&Bs[kk * B_STRIDE + tx * 4];
            float a[8] = {a0.x, a0.y, a0.z, a0.w, a1.x, a1.y, a1.z, a1.w};
            float b[4] = {bb.x, bb.y, bb.z, bb.w};
            #pragma unroll
            for (int i = 0; i < 8; i++)
                #pragma unroll
                for (int j = 0; j < 4; j++)
                    acc[i][j] += a[i] * b[j];
        }
        __syncthreads();
    }
    #pragma unroll
    for (int i = 0; i < 8; i++) {
        int gr = m0 + ty * 8 + i;
        float* cp = C + (size_t)gr * ldC + n0 + tx * 4;
        #pragma unroll
        for (int j = 0; j < 4; j++) {
            float v = acc[i][j] + bias[n0 + tx * 4 + j];
            if (act_gelu) v = gelu_f(v);
            cp[j] = v;
        }
    }
}

// ---------------------------------------------------------------------------
__global__ void c2_kernel(const float* __restrict__ t1, const float* __restrict__ w,
                          const float* __restrict__ b, float* __restrict__ out) {
    int idx = blockIdx.x * blockDim.x + threadIdx.x;
    if (idx >= NTOKTOT * 2) return;
    int t = idx >> 1, p = idx & 1;
    const float* row = t1 + (size_t)t * 64;
    const float* wp = w + p * 64;
    float s = b[p];
    #pragma unroll
    for (int k = 0; k < 64; k++) s += row[k] * wp[k];
    out[idx] = gelu_f(s);
}

__global__ void final_mul_kernel(const float* __restrict__ o2, float* __restrict__ out) {
    int i = blockIdx.x * blockDim.x + threadIdx.x;
    if (i >= NB * 2 * SPAT) return;
    int b = i / (2 * SPAT);
    int rem = i % (2 * SPAT);
    int p = rem / SPAT;
    int sp = rem % SPAT;
    int t = b * SPAT + sp;
    out[i] = o2[t * 2 + p] * o2[2 * NTOKTOT + t * 2 + p];
}

// ---------------------------------------------------------------------------
extern "C" void kernel_launch(void* const* d_in, const int* in_sizes, int n_in,
                              void* d_out, int out_size) {
    (void)in_sizes; (void)n_in; (void)out_size;
    const float* x      = (const float*)d_in[0];
    const float* n1_g   = (const float*)d_in[1];
    const float* n1_b   = (const float*)d_in[2];
    const float* qkv_w  = (const float*)d_in[3];
    const float* qkv_b  = (const float*)d_in[4];
    const float* proj_w = (const float*)d_in[5];
    const float* proj_b = (const float*)d_in[6];
    const float* rpb    = (const float*)d_in[7];
    const float* n2_g   = (const float*)d_in[8];
    const float* n2_b   = (const float*)d_in[9];
    const float* fc1_w  = (const float*)d_in[10];
    const float* fc1_b  = (const float*)d_in[11];
    const float* fc2_w  = (const float*)d_in[12];
    const float* fc2_b  = (const float*)d_in[13];
    const float* hln_g  = (const float*)d_in[14];
    const float* hln_b  = (const float*)d_in[15];
    const float* c1_w   = (const float*)d_in[16];
    const float* c1_b   = (const float*)d_in[17];
    const float* c2_w   = (const float*)d_in[18];
    const float* c2_b   = (const float*)d_in[19];
    const int*   rpi    = (const int*)d_in[20];
    float* out = (float*)d_out;

    float *xcur, *biasbuf, *c1buf, *out2;
    __half *bufA, *bufB, *qkvh, *bigh, *wqkv, *wproj, *wfc1, *wfc2;
    int *map0, *map1, *lab;
    cudaGetSymbolAddress((void**)&xcur,    g_xcur);
    cudaGetSymbolAddress((void**)&bufA,    g_bufA);
    cudaGetSymbolAddress((void**)&bufB,    g_bufB);
    cudaGetSymbolAddress((void**)&qkvh,    g_qkvh);
    cudaGetSymbolAddress((void**)&bigh,    g_bigh);
    cudaGetSymbolAddress((void**)&biasbuf, g_bias);
    cudaGetSymbolAddress((void**)&c1buf,   g_c1);
    cudaGetSymbolAddress((void**)&out2,    g_out2);
    cudaGetSymbolAddress((void**)&map0,    g_map0);
    cudaGetSymbolAddress((void**)&map1,    g_map1);
    cudaGetSymbolAddress((void**)&lab,     g_lab);
    cudaGetSymbolAddress((void**)&wqkv,    g_wqkv);
    cudaGetSymbolAddress((void**)&wproj,   g_wproj);
    cudaGetSymbolAddress((void**)&wfc1,    g_wfc1);
    cudaGetSymbolAddress((void**)&wfc2,    g_wfc2);

    cudaFuncSetAttribute(attn_mma_kernel, cudaFuncAttributeMaxDynamicSharedMemorySize, ATTN_SMEM_B);
    cudaFuncSetAttribute(gemm_h_kernel, cudaFuncAttributeMaxDynamicSharedMemorySize, HGEMM_SMEM);

    build_maps_kernel<<<(NTOKTOT + 255) / 256, 256>>>(map0, map1, lab);
    w2h_kernel<<<1024, 256>>>(qkv_w,  wqkv,  4 * QKVC * CDIM / 4);
    w2h_kernel<<<1024, 256>>>(proj_w, wproj, 4 * CDIM * CDIM / 4);
    w2h_kernel<<<1024, 256>>>(fc1_w,  wfc1,  4 * MLPC * CDIM / 4);
    w2h_kernel<<<1024, 256>>>(fc2_w,  wfc2,  4 * CDIM * MLPC / 4);

    auto gemm = [&](const __half* A, const __half* W, const float* bias, void* C,
                    int M, int N, int K, int ldC, int gelu, const int* scat,
                    int resid, int out_half) {
        dim3 grid(N / 256, M / 128);
        gemm_h_kernel<<<grid, 256, HGEMM_SMEM>>>(A, W, bias, C, M, N, K, ldC,
                                                 gelu, scat, resid, out_half);
    };

    for (int br = 0; br < 2; br++) {
        {
            dim3 blk(32, 8), grd(SPAT / 32, CDIM / 32, NB);
            transpose_in_kernel<<<grd, blk>>>(x, xcur);
        }
        for (int bl = 0; bl < 2; bl++) {
            int ib = br * 2 + bl;
            int shifted = bl;
            const int* map = shifted ? map1 : map0;

            bias_gather_kernel<<<(NHEADS * BIAS_HN + 255) / 256, 256>>>(
                rpb + (size_t)ib * RPBN * NHEADS, rpi, biasbuf);

            ln_kernel<<<NTOKTOT, 256>>>(xcur, n1_g + ib * CDIM, n1_b + ib * CDIM, bufA, map);

            gemm(bufA, wqkv + (size_t)ib * QKVC * CDIM, qkv_b + ib * QKVC,
                 qkvh, NTOKTOT, QKVC, CDIM, QKVC, 0, nullptr, 0, 1);

            {
                dim3 grd(NHEADS, NWIN);
                attn_mma_kernel<<<grd, 256, ATTN_SMEM_B>>>(qkvh, biasbuf, lab, bufB, shifted);
            }

            gemm(bufB, wproj + (size_t)ib * CDIM * CDIM, proj_b + ib * CDIM,
                 xcur, NTOKTOT, CDIM, CDIM, CDIM, 0, map, 1, 0);

            ln_kernel<<<NTOKTOT, 256>>>(xcur, n2_g + ib * CDIM, n2_b + ib * CDIM, bufA, nullptr);

            gemm(bufA, wfc1 + (size_t)ib * MLPC * CDIM, fc1_b + ib * MLPC,
                 bigh, NTOKTOT, MLPC, CDIM, MLPC, 1, nullptr, 0, 1);

            gemm(bigh, wfc2 + (size_t)ib * CDIM * MLPC, fc2_b + ib * CDIM,
                 xcur, NTOKTOT, CDIM, MLPC, CDIM, 0, nullptr, 1, 0);
        }
        ln_kernel<<<NTOKTOT, 256>>>(xcur, hln_g + br * CDIM, hln_b + br * CDIM, bufA, nullptr);
        {
            dim3 grid(1, NTOKTOT / GBM);
            gemm_small_kernel<<<grid, 256>>>(bufA, c1_w + (size_t)br * 64 * CDIM,
                                             c1_b + br * 64, c1buf, NTOKTOT, 64, CDIM, 64, 1);
        }
        c2_kernel<<<(NTOKTOT * 2 + 255) / 256, 256>>>(
            c1buf, c2_w + br * 2 * 64, c2_b + br * 2, out2 + (size_t)br * NTOKTOT * 2);
    }
    final_mul_kernel<<<(NB * 2 * SPAT + 255) / 256, 256>>>(out2, out);
}

// round 8
// speedup vs baseline: 5.7920x; 1.1494x over previous
#include <cuda_runtime.h>
#include <cuda_fp16.h>
#include <math.h>

// ---------------------------------------------------------------------------
#define NB      2
#define CDIM    768
#define DD      16
#define HH      14
#define WW      14
#define SPAT    (DD*HH*WW)        // 3136
#define NTOKTOT (NB*SPAT)         // 6272
#define NWIN    16
#define NWINB   8
#define NTOK    392
#define NHEADS  24
#define HDIM    32
#define QKVC    (3*CDIM)          // 2304
#define MLPC    (4*CDIM)          // 3072
#define RPBN    2535
#define BIAS_HN (NTOK*NTOK)

// ---------------------------------------------------------------------------
// Per-branch scratch (x2 for concurrent branches)
__device__ __align__(128) float  g_xcur[2*NTOKTOT*CDIM];
__device__ __align__(128) __half g_bufA[2*NTOKTOT*CDIM];
__device__ __align__(128) __half g_bufB[2*NTOKTOT*CDIM];
__device__ __align__(128) __half g_qkvh[2*NTOKTOT*QKVC];
__device__ __align__(128) __half g_bigh[2*NTOKTOT*MLPC];
__device__ __align__(128) __half g_bias[2*NHEADS*BIAS_HN];
__device__ __align__(128) float  g_c1  [2*NTOKTOT*64];
__device__ __align__(128) float  g_out2[2*NTOKTOT*2];
__device__ __align__(128) int    g_map0[NTOKTOT];
__device__ __align__(128) int    g_map1[NTOKTOT];
__device__ __align__(128) int    g_lab [NWINB*NTOK];
__device__ __align__(128) __half g_wqkv[4*QKVC*CDIM];
__device__ __align__(128) __half g_wproj[4*CDIM*CDIM];
__device__ __align__(128) __half g_wfc1[4*MLPC*CDIM];
__device__ __align__(128) __half g_wfc2[4*CDIM*MLPC];

__device__ __forceinline__ float gelu_f(float x) {
    return 0.5f * x * (1.0f + erff(x * 0.70710678118654752440f));
}

__device__ __forceinline__ unsigned pack_h2(float lo, float hi) {
    unsigned r;
    asm("cvt.rn.f16x2.f32 %0, %1, %2;" : "=r"(r) : "f"(hi), "f"(lo));
    return r;
}

__device__ __forceinline__ void cp16(unsigned saddr, const void* g) {
    asm volatile("cp.async.cg.shared.global [%0], [%1], 16;" :: "r"(saddr), "l"(g) : "memory");
}

__device__ __forceinline__ unsigned smem_u32(const void* p) {
    unsigned a;
    asm("{ .reg .u64 t; cvta.to.shared.u64 t, %1; cvt.u32.u64 %0, t; }" : "=r"(a) : "l"(p));
    return a;
}

#define SW128(off) ((off) ^ (((off) >> 3) & 0x70))

#define LDSM_X4(r0, r1, r2, r3, addr) \
    asm volatile("ldmatrix.sync.aligned.m8n8.x4.shared.b16 {%0,%1,%2,%3}, [%4];" \
                 : "=r"(r0), "=r"(r1), "=r"(r2), "=r"(r3) : "r"(addr))

#define MMA_F16(c, a, b0v, b1v) \
    asm volatile("mma.sync.aligned.m16n8k16.row.col.f32.f16.f16.f32 " \
                 "{%0,%1,%2,%3}, {%4,%5,%6,%7}, {%8,%9}, {%0,%1,%2,%3};" \
                 : "+f"((c)[0]), "+f"((c)[1]), "+f"((c)[2]), "+f"((c)[3]) \
                 : "r"((a)[0]), "r"((a)[1]), "r"((a)[2]), "r"((a)[3]), \
                   "r"(b0v), "r"(b1v))

// ---------------------------------------------------------------------------
__global__ void w2h_kernel(const float* __restrict__ in, __half* __restrict__ out, int n4) {
    int i = blockIdx.x * blockDim.x + threadIdx.x;
    for (; i < n4; i += gridDim.x * blockDim.x) {
        float4 v = ((const float4*)in)[i];
        ((__half2*)out)[2*i]   = __floats2half2_rn(v.x, v.y);
        ((__half2*)out)[2*i+1] = __floats2half2_rn(v.z, v.w);
    }
}

__global__ void build_maps_kernel(int* map0, int* map1, int* lab) {
    int r = blockIdx.x * blockDim.x + threadIdx.x;
    if (r < NTOKTOT) {
        int b = r / SPAT, rem = r % SPAT;
        int wi = rem / NTOK, n = rem % NTOK;
        int bd = wi >> 2, bh = (wi >> 1) & 1, bw = wi & 1;
        int wd = n / 49, wh = (n / 7) % 7, ww = n % 7;
        int d = bd * 8 + wd, h = bh * 7 + wh, w = bw * 7 + ww;
        map0[r] = b * SPAT + d * (HH*WW) + h * WW + w;
        int ds = (d + 4) & 15, hs = (h + 3) % 14, ws = (w + 3) % 14;
        map1[r] = b * SPAT + ds * (HH*WW) + hs * WW + ws;
    }
    if (r < NWINB * NTOK) {
        int wi = r / NTOK, n = r % NTOK;
        int bd = wi >> 2, bh = (wi >> 1) & 1, bw = wi & 1;
        int wd = n / 49, wh = (n / 7) % 7, ww = n % 7;
        int d = bd * 8 + wd, h = bh * 7 + wh, w = bw * 7 + ww;
        int cd = d < 8 ? 0 : (d < 12 ? 1 : 2);
        int ch = h < 7 ? 0 : (h < 11 ? 1 : 2);
        int cw = w < 7 ? 0 : (w < 11 ? 1 : 2);
        lab[r] = cd * 9 + ch * 3 + cw;
    }
}

__global__ void transpose_in_kernel(const float* __restrict__ x, float* __restrict__ out) {
    __shared__ float tile[32][33];
    int b  = blockIdx.z;
    int s0 = blockIdx.x * 32, c0 = blockIdx.y * 32;
    int tx = threadIdx.x, ty = threadIdx.y;
    #pragma unroll
    for (int i = 0; i < 32; i += 8) {
        int c = c0 + ty + i, s = s0 + tx;
        if (c < CDIM && s < SPAT)
            tile[ty + i][tx] = x[((size_t)b * CDIM + c) * SPAT + s];
    }
    __syncthreads();
    #pragma unroll
    for (int i = 0; i < 32; i += 8) {
        int s = s0 + ty + i, c = c0 + tx;
        if (s < SPAT && c < CDIM)
            out[((size_t)b * SPAT + s) * CDIM + c] = tile[tx][ty + i];
    }
}

__global__ void bias_gather_kernel(const float* __restrict__ rpb,
                                   const int* __restrict__ rpi,
                                   __half* __restrict__ biasT) {
    int idx = blockIdx.x * blockDim.x + threadIdx.x;
    if (idx >= NHEADS * BIAS_HN) return;
    int h  = idx / BIAS_HN;
    int nm = idx % BIAS_HN;
    biasT[idx] = __float2half_rn(rpb[rpi[nm] * NHEADS + h]);
}

// ---------------------------------------------------------------------------
__global__ void __launch_bounds__(256) ln_kernel(const float* __restrict__ in,
                                                 const float* __restrict__ gw,
                                                 const float* __restrict__ gb,
                                                 __half* __restrict__ out,
                                                 const int* __restrict__ map) {
    int r = blockIdx.x;
    int src = map ? map[r] : r;
    const float* x = in + (size_t)src * CDIM;
    int t = threadIdx.x;
    float v0 = x[t], v1 = x[t + 256], v2 = x[t + 512];
    __shared__ float red[8];
    __shared__ float stat[2];
    float s = v0 + v1 + v2;
    #pragma unroll
    for (int o = 16; o; o >>= 1) s += __shfl_xor_sync(0xffffffffu, s, o);
    if ((t & 31) == 0) red[t >> 5] = s;
    __syncthreads();
    if (t < 8) {
        float z = red[t];
        z += __shfl_xor_sync(0xffu, z, 4);
        z += __shfl_xor_sync(0xffu, z, 2);
        z += __shfl_xor_sync(0xffu, z, 1);
        if (t == 0) stat[0] = z * (1.0f / CDIM);
    }
    __syncthreads();
    float mu = stat[0];
    float d0 = v0 - mu, d1 = v1 - mu, d2 = v2 - mu;
    s = d0 * d0 + d1 * d1 + d2 * d2;
    #pragma unroll
    for (int o = 16; o; o >>= 1) s += __shfl_xor_sync(0xffffffffu, s, o);
    if ((t & 31) == 0) red[t >> 5] = s;
    __syncthreads();
    if (t < 8) {
        float z = red[t];
        z += __shfl_xor_sync(0xffu, z, 4);
        z += __shfl_xor_sync(0xffu, z, 2);
        z += __shfl_xor_sync(0xffu, z, 1);
        if (t == 0) stat[1] = rsqrtf(z * (1.0f / CDIM) + 1e-5f);
    }
    __syncthreads();
    float inv = stat[1];
    __half* o = out + (size_t)r * CDIM;
    o[t]       = __float2half_rn(d0 * inv * gw[t]       + gb[t]);
    o[t + 256] = __float2half_rn(d1 * inv * gw[t + 256] + gb[t + 256]);
    o[t + 512] = __float2half_rn(d2 * inv * gw[t + 512] + gb[t + 512]);
}

// ---------------------------------------------------------------------------
// FP16 GEMM: CTA 128x256, BK=64, warp tile 64x64 (2Mx4N), 3-stage cp.async,
// one sync per tile. SW128 swizzled smem, ldmatrix, mma.m16n8k16 fp32 acc.
// ---------------------------------------------------------------------------
#define HASTG 16384
#define HBSTG 32768
#define HGEMM_SMEM (3*HASTG + 3*HBSTG)   // 147456 B

__global__ void __launch_bounds__(256) gemm_h_kernel(
    const __half* __restrict__ A, const __half* __restrict__ W,
    const float* __restrict__ bias, void* __restrict__ Cv,
    int M, int N, int K, int ldC,
    int act_gelu, const int* __restrict__ scatter, int add_resid, int out_half)
{
    extern __shared__ __align__(128) char smg[];
    unsigned sbase = smem_u32(smg);
    unsigned bbase = sbase + 3 * HASTG;
    int tid = threadIdx.x, warp = tid >> 5, lane = tid & 31;
    int wm = warp >> 2, wn = warp & 3;
    int gid = lane >> 2, tig = lane & 3;
    int m0 = blockIdx.y * 128, n0 = blockIdx.x * 256;

    const __half* Ap = A + (size_t)m0 * K;
    const __half* Wp = W + (size_t)n0 * K;
    int NT = K >> 6;

    int ldrow = tid >> 3;
    int ldc   = tid & 7;

    int l7 = lane & 7;
    int a_row = ((lane >> 3) & 1) * 8 + l7;
    int a_cs  = lane >> 4;
    int b_row = ((lane >> 4) & 1) * 8 + l7;
    int b_cs  = (lane >> 3) & 1;

    float acc[4][8][4];
    #pragma unroll
    for (int mi = 0; mi < 4; mi++)
        #pragma unroll
        for (int nj = 0; nj < 8; nj++)
            #pragma unroll
            for (int r = 0; r < 4; r++) acc[mi][nj][r] = 0.0f;

    #pragma unroll
    for (int t = 0; t < 2; t++) {
        #pragma unroll
        for (int l = 0; l < 4; l++) {
            int row = ldrow + l * 32;
            unsigned off = SW128((unsigned)(row * 128 + ldc * 16));
            cp16(sbase + t * HASTG + off, Ap + (size_t)row * K + t * 64 + ldc * 8);
        }
        #pragma unroll
        for (int l = 0; l < 8; l++) {
            int row = ldrow + l * 32;
            unsigned off = SW128((unsigned)(row * 128 + ldc * 16));
            cp16(bbase + t * HBSTG + off, Wp + (size_t)row * K + t * 64 + ldc * 8);
        }
        asm volatile("cp.async.commit_group;" ::: "memory");
    }

    for (int t = 0; t < NT; t++) {
        if (t + 1 < NT) asm volatile("cp.async.wait_group 1;" ::: "memory");
        else            asm volatile("cp.async.wait_group 0;" ::: "memory");
        __syncthreads();
        if (t + 2 < NT) {
            int s2 = (t + 2) % 3;
            #pragma unroll
            for (int l = 0; l < 4; l++) {
                int row = ldrow + l * 32;
                unsigned off = SW128((unsigned)(row * 128 + ldc * 16));
                cp16(sbase + s2 * HASTG + off, Ap + (size_t)row * K + (t+2) * 64 + ldc * 8);
            }
            #pragma unroll
            for (int l = 0; l < 8; l++) {
                int row = ldrow + l * 32;
                unsigned off = SW128((unsigned)(row * 128 + ldc * 16));
                cp16(bbase + s2 * HBSTG + off, Wp + (size_t)row * K + (t+2) * 64 + ldc * 8);
            }
            asm volatile("cp.async.commit_group;" ::: "memory");
        }
        unsigned sA = sbase + (t % 3) * HASTG;
        unsigned sB = bbase + (t % 3) * HBSTG;

        #pragma unroll
        for (int s = 0; s < 4; s++) {
            unsigned af[4][4], bf[8][2];
            #pragma unroll
            for (int mi = 0; mi < 4; mi++) {
                int row = wm * 64 + mi * 16 + a_row;
                int ch  = 2 * s + a_cs;
                unsigned ad = sA + SW128((unsigned)(row * 128 + ch * 16));
                LDSM_X4(af[mi][0], af[mi][1], af[mi][2], af[mi][3], ad);
            }
            #pragma unroll
            for (int np = 0; np < 4; np++) {
                int row = wn * 64 + np * 16 + b_row;
                int ch  = 2 * s + b_cs;
                unsigned bd = sB + SW128((unsigned)(row * 128 + ch * 16));
                LDSM_X4(bf[2*np][0], bf[2*np][1], bf[2*np+1][0], bf[2*np+1][1], bd);
            }
            #pragma unroll
            for (int mi = 0; mi < 4; mi++)
                #pragma unroll
                for (int nj = 0; nj < 8; nj++)
                    MMA_F16(acc[mi][nj], af[mi], bf[nj][0], bf[nj][1]);
        }
    }

    float bs0[8], bs1[8];
    #pragma unroll
    for (int nj = 0; nj < 8; nj++) {
        int col = n0 + wn * 64 + nj * 8 + 2 * tig;
        bs0[nj] = bias[col];
        bs1[nj] = bias[col + 1];
    }
    #pragma unroll
    for (int mi = 0; mi < 4; mi++) {
        #pragma unroll
        for (int half = 0; half < 2; half++) {
            int gr = m0 + wm * 64 + mi * 16 + gid + half * 8;
            int tr = scatter ? scatter[gr] : gr;
            #pragma unroll
            for (int nj = 0; nj < 8; nj++) {
                int col = n0 + wn * 64 + nj * 8 + 2 * tig;
                float v0 = acc[mi][nj][half * 2 + 0] + bs0[nj];
                float v1 = acc[mi][nj][half * 2 + 1] + bs1[nj];
                if (act_gelu) { v0 = gelu_f(v0); v1 = gelu_f(v1); }
                if (out_half) {
                    unsigned* hp = (unsigned*)((__half*)Cv + (size_t)tr * ldC + col);
                    *hp = pack_h2(v0, v1);
                } else {
                    float* cp = (float*)Cv + (size_t)tr * ldC + col;
                    if (add_resid) { v0 += cp[0]; v1 += cp[1]; }
                    cp[0] = v0; cp[1] = v1;
                }
            }
        }
    }
}

// ---------------------------------------------------------------------------
// Tensor-core window attention, fp16 bias table.
// ---------------------------------------------------------------------------
#define QS_STRIDE 40
#define VT_STRIDE 408
#define ATTN_SMEM_B (400*QS_STRIDE*2*2 + 32*VT_STRIDE*2 + 400*4)

__global__ void __launch_bounds__(256) attn_mma_kernel(
    const __half* __restrict__ qkv,
    const __half* __restrict__ biasT,
    const int* __restrict__ labels,
    __half* __restrict__ out, int shifted)
{
    extern __shared__ __align__(16) char smA[];
    __half* Qs = (__half*)smA;
    __half* Ks = Qs + 400 * QS_STRIDE;
    __half* Vt = Ks + 400 * QS_STRIDE;
    int* lab = (int*)(Vt + 32 * VT_STRIDE);
    int h = blockIdx.x, w = blockIdx.y;
    int tid = threadIdx.x;
    int rbase = w * NTOK;

    for (int i = tid; i < (400*QS_STRIDE*2*2 + 32*VT_STRIDE*2) / 16; i += 256)
        ((uint4*)smA)[i] = make_uint4(0, 0, 0, 0);
    __syncthreads();

    for (int i = tid; i < 392 * 4; i += 256) {
        int m = i >> 2, c = i & 3;
        const __half* base = qkv + (size_t)(rbase + m) * QKVC + h * HDIM + c * 8;
        *(uint4*)(Qs + m * QS_STRIDE + c * 8) = *(const uint4*)(base);
        *(uint4*)(Ks + m * QS_STRIDE + c * 8) = *(const uint4*)(base + CDIM);
    }
    for (int m = tid; m < 392; m += 256) {
        const __half* vp = qkv + (size_t)(rbase + m) * QKVC + 2 * CDIM + h * HDIM;
        #pragma unroll
        for (int d = 0; d < 32; d++) Vt[d * VT_STRIDE + m] = vp[d];
    }
    for (int i = tid; i < 400; i += 256)
        lab[i] = (shifted && i < NTOK) ? labels[(w & 7) * NTOK + i] : 0;
    __syncthreads();

    int warp = tid >> 5, lane = tid & 31;
    int gid = lane >> 2, tig = lane & 3;
    int l7 = lane & 7;
    int a_row = ((lane >> 3) & 1) * 8 + l7;
    int a_cs  = lane >> 4;
    int b_row = ((lane >> 4) & 1) * 8 + l7;
    int b_cs  = (lane >> 3) & 1;
    const float scale = 0.17677669529663689f;

    unsigned qsb = smem_u32(Qs);
    unsigned ksb = smem_u32(Ks);
    unsigned vtb = smem_u32(Vt);

    for (int mt = warp; mt < 25; mt += 8) {
        unsigned aq[2][4];
        #pragma unroll
        for (int s = 0; s < 2; s++) {
            unsigned ad = qsb + (unsigned)(((mt * 16 + a_row) * QS_STRIDE + (2*s + a_cs) * 8) * 2);
            LDSM_X4(aq[s][0], aq[s][1], aq[s][2], aq[s][3], ad);
        }
        int q0 = mt * 16 + gid, q1 = q0 + 8;
        int q1ok = (mt != 24);
        int labq0 = lab[q0], labq1 = lab[q1];
        const __half* bp0 = biasT + ((size_t)h * NTOK + q0) * NTOK;
        const __half* bp1 = q1ok ? biasT + ((size_t)h * NTOK + q1) * NTOK : biasT;

        float mr0 = -1e30f, mr1 = -1e30f, lr0 = 0.f, lr1 = 0.f;
        float acc[4][4];
        #pragma unroll
        for (int j = 0; j < 4; j++)
            #pragma unroll
            for (int r = 0; r < 4; r++) acc[j][r] = 0.f;

        for (int nt = 0; nt < 25; nt++) {
            float c0[4] = {0.f, 0.f, 0.f, 0.f};
            float c1[4] = {0.f, 0.f, 0.f, 0.f};
            #pragma unroll
            for (int s = 0; s < 2; s++) {
                unsigned bd = ksb + (unsigned)(((nt * 16 + b_row) * QS_STRIDE + (2*s + b_cs) * 8) * 2);
                unsigned bf0, bf1, bf2, bf3;
                LDSM_X4(bf0, bf1, bf2, bf3, bd);
                MMA_F16(c0, aq[s], bf0, bf1);
                MMA_F16(c1, aq[s], bf2, bf3);
            }
            float sv[2][4];
            #pragma unroll
            for (int f = 0; f < 2; f++) {
                float* c = f ? c1 : c0;
                int k0 = nt * 16 + f * 8 + 2 * tig;
                int kvalid = !(nt == 24 && f == 1);
                if (kvalid) {
                    __half2 hb0 = *(const __half2*)(bp0 + k0);
                    float b00 = __low2float(hb0), b01 = __high2float(hb0);
                    float b10 = 0.f, b11 = 0.f;
                    if (q1ok) {
                        __half2 hb1 = *(const __half2*)(bp1 + k0);
                        b10 = __low2float(hb1); b11 = __high2float(hb1);
                    }
                    float mk0 = 0.f, mk1 = 0.f;
                    if (shifted) {
                        int lk0 = lab[k0], lk1 = lab[k0 + 1];
                        mk0 = (lk0 != labq0) ? -100.f : 0.f;
                        mk1 = (lk1 != labq0) ? -100.f : 0.f;
                        b10 += (lk0 != labq1) ? -100.f : 0.f;
                        b11 += (lk1 != labq1) ? -100.f : 0.f;
                    }
                    sv[f][0] = c[0] * scale + b00 + mk0;
                    sv[f][1] = c[1] * scale + b01 + mk1;
                    sv[f][2] = c[2] * scale + b10;
                    sv[f][3] = c[3] * scale + b11;
                } else {
                    sv[f][0] = sv[f][1] = sv[f][2] = sv[f][3] = -1e30f;
                }
            }
            float tm0 = fmaxf(fmaxf(sv[0][0], sv[0][1]), fmaxf(sv[1][0], sv[1][1]));
            float tm1 = fmaxf(fmaxf(sv[0][2], sv[0][3]), fmaxf(sv[1][2], sv[1][3]));
            tm0 = fmaxf(tm0, __shfl_xor_sync(0xffffffffu, tm0, 1));
            tm0 = fmaxf(tm0, __shfl_xor_sync(0xffffffffu, tm0, 2));
            tm1 = fmaxf(tm1, __shfl_xor_sync(0xffffffffu, tm1, 1));
            tm1 = fmaxf(tm1, __shfl_xor_sync(0xffffffffu, tm1, 2));
            float mn0 = fmaxf(mr0, tm0), mn1 = fmaxf(mr1, tm1);
            float al0 = __expf(mr0 - mn0), al1 = __expf(mr1 - mn1);
            float e[2][4];
            #pragma unroll
            for (int f = 0; f < 2; f++) {
                e[f][0] = __expf(sv[f][0] - mn0);
                e[f][1] = __expf(sv[f][1] - mn0);
                e[f][2] = __expf(sv[f][2] - mn1);
                e[f][3] = __expf(sv[f][3] - mn1);
            }
            float ts0 = e[0][0] + e[0][1] + e[1][0] + e[1][1];
            float ts1 = e[0][2] + e[0][3] + e[1][2] + e[1][3];
            ts0 += __shfl_xor_sync(0xffffffffu, ts0, 1);
            ts0 += __shfl_xor_sync(0xffffffffu, ts0, 2);
            ts1 += __shfl_xor_sync(0xffffffffu, ts1, 1);
            ts1 += __shfl_xor_sync(0xffffffffu, ts1, 2);
            lr0 = lr0 * al0 + ts0;
            lr1 = lr1 * al1 + ts1;
            mr0 = mn0; mr1 = mn1;
            #pragma unroll
            for (int j = 0; j < 4; j++) {
                acc[j][0] *= al0; acc[j][1] *= al0;
                acc[j][2] *= al1; acc[j][3] *= al1;
            }
            unsigned pa[4];
            pa[0] = pack_h2(e[0][0], e[0][1]);
            pa[1] = pack_h2(e[0][2], e[0][3]);
            pa[2] = pack_h2(e[1][0], e[1][1]);
            pa[3] = pack_h2(e[1][2], e[1][3]);
            #pragma unroll
            for (int g = 0; g < 2; g++) {
                unsigned bd = vtb + (unsigned)(((g * 16 + b_row) * VT_STRIDE + nt * 16 + b_cs * 8) * 2);
                unsigned bf0, bf1, bf2, bf3;
                LDSM_X4(bf0, bf1, bf2, bf3, bd);
                MMA_F16(acc[2*g],   pa, bf0, bf1);
                MMA_F16(acc[2*g+1], pa, bf2, bf3);
            }
        }
        float li0 = 1.0f / lr0, li1 = 1.0f / lr1;
        if (q0 < NTOK) {
            __half* op = out + (size_t)(rbase + q0) * CDIM + h * HDIM;
            #pragma unroll
            for (int j = 0; j < 4; j++)
                *(unsigned*)(op + j * 8 + 2 * tig) = pack_h2(acc[j][0] * li0, acc[j][1] * li0);
        }
        if (q1ok) {
            __half* op = out + (size_t)(rbase + q1) * CDIM + h * HDIM;
            #pragma unroll
            for (int j = 0; j < 4; j++)
                *(unsigned*)(op + j * 8 + 2 * tig) = pack_h2(acc[j][2] * li1, acc[j][3] * li1);
        }
    }
}

// ---------------------------------------------------------------------------
// Small GEMM (head conv, N=64): SIMT, half A, fp32 W
// ---------------------------------------------------------------------------
#define GBM 128
#define GBK 16
#define A_STRIDE 132
#define B_STRIDE 68

__global__ void __launch_bounds__(256) gemm_small_kernel(
    const __half* __restrict__ A, const float* __restrict__ W,
    const float* __restrict__ bias, float* __restrict__ C,
    int M, int N, int K, int ldC, int act_gelu)
{
    __shared__ float As[GBK * A_STRIDE];
    __shared__ float Bs[GBK * B_STRIDE];
    int tid = threadIdx.x;
    int tx = tid & 15, ty = tid >> 4;
    int m0 = blockIdx.y * GBM, n0 = blockIdx.x * 64;
    const __half* Aptr = A + (size_t)m0 * K;
    const float* Wptr = W + (size_t)n0 * K;
    float acc[8][4];
    #pragma unroll
    for (int i = 0; i < 8; i++)
        #pragma unroll
        for (int j = 0; j < 4; j++) acc[i][j] = 0.0f;

    for (int k0 = 0; k0 < K; k0 += GBK) {
        #pragma unroll
        for (int l = 0; l < 2; l++) {
            int f = tid + l * 256;
            int row = f >> 2, kc = (f & 3) * 4;
            const __half* ap = Aptr + (size_t)row * K + k0 + kc;
            __half2 h0 = *(const __half2*)(ap);
            __half2 h1 = *(const __half2*)(ap + 2);
            As[(kc + 0) * A_STRIDE + row] = __low2float(h0);
            As[(kc + 1) * A_STRIDE + row] = __high2float(h0);
            As[(kc + 2) * A_STRIDE + row] = __low2float(h1);
            As[(kc + 3) * A_STRIDE + row] = __high2float(h1);
        }
        {
            int row = tid >> 2, kc = (tid & 3) * 4;
            float4 v = *(const float4*)(Wptr + (size_t)row * K + k0 + kc);
            Bs[(kc + 0) * B_STRIDE + row] = v.x;
            Bs[(kc + 1) * B_STRIDE + row] = v.y;
            Bs[(kc + 2) * B_STRIDE + row] = v.z;
            Bs[(kc + 3) * B_STRIDE + row] = v.w;
        }
        __syncthreads();
        #pragma unroll
        for (int kk = 0; kk < GBK; kk++) {
            float4 a0 = *(const float4*)&As[kk * A_STRIDE + ty * 8];
            float4 a1 = *(const float4*)&As[kk * A_STRIDE + ty * 8 + 4];
            float4 bb = *(const float4*)&Bs[kk * B_STRIDE + tx * 4];
            float a[8] = {a0.x, a0.y, a0.z, a0.w, a1.x, a1.y, a1.z, a1.w};
            float b[4] = {bb.x, bb.y, bb.z, bb.w};
            #pragma unroll
            for (int i = 0; i < 8; i++)
                #pragma unroll
                for (int j = 0; j < 4; j++)
                    acc[i][j] += a[i] * b[j];
        }
        __syncthreads();
    }
    #pragma unroll
    for (int i = 0; i < 8; i++) {
        int gr = m0 + ty * 8 + i;
        float* cp = C + (size_t)gr * ldC + n0 + tx * 4;
        #pragma unroll
        for (int j = 0; j < 4; j++) {
            float v = acc[i][j] + bias[n0 + tx * 4 + j];
            if (act_gelu) v = gelu_f(v);
            cp[j] = v;
        }
    }
}

// ---------------------------------------------------------------------------
__global__ void c2_kernel(const float* __restrict__ t1, const float* __restrict__ w,
                          const float* __restrict__ b, float* __restrict__ out) {
    int idx = blockIdx.x * blockDim.x + threadIdx.x;
    if (idx >= NTOKTOT * 2) return;
    int t = idx >> 1, p = idx & 1;
    const float* row = t1 + (size_t)t * 64;
    const float* wp = w + p * 64;
    float s = b[p];
    #pragma unroll
    for (int k = 0; k < 64; k++) s += row[k] * wp[k];
    out[idx] = gelu_f(s);
}

__global__ void final_mul_kernel(const float* __restrict__ o2, float* __restrict__ out) {
    int i = blockIdx.x * blockDim.x + threadIdx.x;
    if (i >= NB * 2 * SPAT) return;
    int b = i / (2 * SPAT);
    int rem = i % (2 * SPAT);
    int p = rem / SPAT;
    int sp = rem % SPAT;
    int t = b * SPAT + sp;
    out[i] = o2[t * 2 + p] * o2[2 * NTOKTOT + t * 2 + p];
}

// ---------------------------------------------------------------------------
extern "C" void kernel_launch(void* const* d_in, const int* in_sizes, int n_in,
                              void* d_out, int out_size) {
    (void)in_sizes; (void)n_in; (void)out_size;
    const float* x      = (const float*)d_in[0];
    const float* n1_g   = (const float*)d_in[1];
    const float* n1_b   = (const float*)d_in[2];
    const float* qkv_w  = (const float*)d_in[3];
    const float* qkv_b  = (const float*)d_in[4];
    const float* proj_w = (const float*)d_in[5];
    const float* proj_b = (const float*)d_in[6];
    const float* rpb    = (const float*)d_in[7];
    const float* n2_g   = (const float*)d_in[8];
    const float* n2_b   = (const float*)d_in[9];
    const float* fc1_w  = (const float*)d_in[10];
    const float* fc1_b  = (const float*)d_in[11];
    const float* fc2_w  = (const float*)d_in[12];
    const float* fc2_b  = (const float*)d_in[13];
    const float* hln_g  = (const float*)d_in[14];
    const float* hln_b  = (const float*)d_in[15];
    const float* c1_w   = (const float*)d_in[16];
    const float* c1_b   = (const float*)d_in[17];
    const float* c2_w   = (const float*)d_in[18];
    const float* c2_b   = (const float*)d_in[19];
    const int*   rpi    = (const int*)d_in[20];
    float* out = (float*)d_out;

    float *xcur0, *c1buf0, *out2;
    __half *bufA0, *bufB0, *qkvh0, *bigh0, *bias0;
    __half *wqkv, *wproj, *wfc1, *wfc2;
    int *map0, *map1, *lab;
    cudaGetSymbolAddress((void**)&xcur0,   g_xcur);
    cudaGetSymbolAddress((void**)&bufA0,   g_bufA);
    cudaGetSymbolAddress((void**)&bufB0,   g_bufB);
    cudaGetSymbolAddress((void**)&qkvh0,   g_qkvh);
    cudaGetSymbolAddress((void**)&bigh0,   g_bigh);
    cudaGetSymbolAddress((void**)&bias0,   g_bias);
    cudaGetSymbolAddress((void**)&c1buf0,  g_c1);
    cudaGetSymbolAddress((void**)&out2,    g_out2);
    cudaGetSymbolAddress((void**)&map0,    g_map0);
    cudaGetSymbolAddress((void**)&map1,    g_map1);
    cudaGetSymbolAddress((void**)&lab,     g_lab);
    cudaGetSymbolAddress((void**)&wqkv,    g_wqkv);
    cudaGetSymbolAddress((void**)&wproj,   g_wproj);
    cudaGetSymbolAddress((void**)&wfc1,    g_wfc1);
    cudaGetSymbolAddress((void**)&wfc2,    g_wfc2);

    cudaFuncSetAttribute(attn_mma_kernel, cudaFuncAttributeMaxDynamicSharedMemorySize, ATTN_SMEM_B);
    cudaFuncSetAttribute(gemm_h_kernel, cudaFuncAttributeMaxDynamicSharedMemorySize, HGEMM_SMEM);

    // one-time infra handles (host-side only; no device memory)
    static cudaStream_t s_br1 = nullptr;
    static cudaEvent_t ev_fork = nullptr, ev_join = nullptr;
    if (s_br1 == nullptr) {
        cudaStreamCreateWithFlags(&s_br1, cudaStreamNonBlocking);
        cudaEventCreateWithFlags(&ev_fork, cudaEventDisableTiming);
        cudaEventCreateWithFlags(&ev_join, cudaEventDisableTiming);
    }

    build_maps_kernel<<<(NTOKTOT + 255) / 256, 256, 0, 0>>>(map0, map1, lab);
    cudaEventRecord(ev_fork, 0);
    cudaStreamWaitEvent(s_br1, ev_fork, 0);

    auto gemm = [&](cudaStream_t st, const __half* A, const __half* W, const float* bias,
                    void* C, int M, int N, int K, int ldC, int gelu, const int* scat,
                    int resid, int out_half) {
        dim3 grid(N / 256, M / 128);
        gemm_h_kernel<<<grid, 256, HGEMM_SMEM, st>>>(A, W, bias, C, M, N, K, ldC,
                                                     gelu, scat, resid, out_half);
    };

    for (int br = 0; br < 2; br++) {
        cudaStream_t st = br ? s_br1 : (cudaStream_t)0;
        float*  xcur  = xcur0  + (size_t)br * NTOKTOT * CDIM;
        __half* bufA  = bufA0  + (size_t)br * NTOKTOT * CDIM;
        __half* bufB  = bufB0  + (size_t)br * NTOKTOT * CDIM;
        __half* qkvh  = qkvh0  + (size_t)br * NTOKTOT * QKVC;
        __half* bigh  = bigh0  + (size_t)br * NTOKTOT * MLPC;
        __half* biasb = bias0  + (size_t)br * NHEADS * BIAS_HN;
        float*  c1buf = c1buf0 + (size_t)br * NTOKTOT * 64;

        // convert this branch's weights (2 layers each)
        w2h_kernel<<<512, 256, 0, st>>>(qkv_w + (size_t)br * 2 * QKVC * CDIM,
                                        wqkv + (size_t)br * 2 * QKVC * CDIM, 2 * QKVC * CDIM / 4);
        w2h_kernel<<<512, 256, 0, st>>>(proj_w + (size_t)br * 2 * CDIM * CDIM,
                                        wproj + (size_t)br * 2 * CDIM * CDIM, 2 * CDIM * CDIM / 4);
        w2h_kernel<<<512, 256, 0, st>>>(fc1_w + (size_t)br * 2 * MLPC * CDIM,
                                        wfc1 + (size_t)br * 2 * MLPC * CDIM, 2 * MLPC * CDIM / 4);
        w2h_kernel<<<512, 256, 0, st>>>(fc2_w + (size_t)br * 2 * CDIM * MLPC,
                                        wfc2 + (size_t)br * 2 * CDIM * MLPC, 2 * CDIM * MLPC / 4);
        {
            dim3 blk(32, 8), grd(SPAT / 32, CDIM / 32, NB);
            transpose_in_kernel<<<grd, blk, 0, st>>>(x, xcur);
        }
        for (int bl = 0; bl < 2; bl++) {
            int ib = br * 2 + bl;
            int shifted = bl;
            const int* map = shifted ? map1 : map0;

            bias_gather_kernel<<<(NHEADS * BIAS_HN + 255) / 256, 256, 0, st>>>(
                rpb + (size_t)ib * RPBN * NHEADS, rpi, biasb);

            ln_kernel<<<NTOKTOT, 256, 0, st>>>(xcur, n1_g + ib * CDIM, n1_b + ib * CDIM, bufA, map);

            gemm(st, bufA, wqkv + (size_t)ib * QKVC * CDIM, qkv_b + ib * QKVC,
                 qkvh, NTOKTOT, QKVC, CDIM, QKVC, 0, nullptr, 0, 1);

            {
                dim3 grd(NHEADS, NWIN);
                attn_mma_kernel<<<grd, 256, ATTN_SMEM_B, st>>>(qkvh, biasb, lab, bufB, shifted);
            }

            gemm(st, bufB, wproj + (size_t)ib * CDIM * CDIM, proj_b + ib * CDIM,
                 xcur, NTOKTOT, CDIM, CDIM, CDIM, 0, map, 1, 0);

            ln_kernel<<<NTOKTOT, 256, 0, st>>>(xcur, n2_g + ib * CDIM, n2_b + ib * CDIM, bufA, nullptr);

            gemm(st, bufA, wfc1 + (size_t)ib * MLPC * CDIM, fc1_b + ib * MLPC,
                 bigh, NTOKTOT, MLPC, CDIM, MLPC, 1, nullptr, 0, 1);

            gemm(st, bigh, wfc2 + (size_t)ib * CDIM * MLPC, fc2_b + ib * CDIM,
                 xcur, NTOKTOT, CDIM, MLPC, CDIM, 0, nullptr, 1, 0);
        }
        ln_kernel<<<NTOKTOT, 256, 0, st>>>(xcur, hln_g + br * CDIM, hln_b + br * CDIM, bufA, nullptr);
        {
            dim3 grid(1, NTOKTOT / GBM);
            gemm_small_kernel<<<grid, 256, 0, st>>>(bufA, c1_w + (size_t)br * 64 * CDIM,
                                                    c1_b + br * 64, c1buf, NTOKTOT, 64, CDIM, 64, 1);
        }
        c2_kernel<<<(NTOKTOT * 2 + 255) / 256, 256, 0, st>>>(
            c1buf, c2_w + br * 2 * 64, c2_b + br * 2, out2 + (size_t)br * NTOKTOT * 2);
    }

    cudaEventRecord(ev_join, s_br1);
    cudaStreamWaitEvent((cudaStream_t)0, ev_join, 0);
    final_mul_kernel<<<(NB * 2 * SPAT + 255) / 256, 256, 0, 0>>>(out2, out);
}